// round 5
// baseline (speedup 1.0000x reference)
#include <cuda_runtime.h>
#include <cuda_fp16.h>
#include <math.h>
#include <stdint.h>

#define NN    50000
#define DD    128
#define EADJ  800000
#define EPRED 500000
#define BNEPS 1e-5f
#define SCANB 196          // ceil(NN/256)
#define NCOPY 32           // stat partial copies

// ---------------- scratch ----------------------------------------------------
__device__ __half2 g_supp_h[NN * (DD / 2)];    // fp16 support
__device__ float g_tmp[NN * DD];
__device__ float g_statpart[2 * NCOPY * 2 * DD];
__device__ float g_bnab[2 * 2 * DD];           // [layer][a(128) | b(128)]
__device__ float g_s1[NN];
__device__ float g_s2[NN];
__device__ int   g_counts[NN];
__device__ int   g_rowstart[NN + 1];
__device__ int   g_cursor[NN];
__device__ int   g_scan_flag[SCANB];           // 0 none, 1 agg, 2 prefix
__device__ int   g_scan_agg[SCANB];
__device__ int   g_scan_pref[SCANB];
__device__ int2  g_csr[EADJ];

// ---------------- helpers ----------------------------------------------------
__device__ __forceinline__ float f2tf32(float f) {
    uint32_t r;
    asm("cvt.rna.tf32.f32 %0, %1;" : "=r"(r) : "f"(f));
    return __uint_as_float(r);
}

__device__ __forceinline__ void mma_tf32(float* c, const uint32_t* a, const uint32_t* b) {
    asm volatile(
        "mma.sync.aligned.m16n8k8.row.col.f32.tf32.tf32.f32 "
        "{%0,%1,%2,%3}, {%4,%5,%6,%7}, {%8,%9}, {%0,%1,%2,%3};\n"
        : "+f"(c[0]), "+f"(c[1]), "+f"(c[2]), "+f"(c[3])
        : "r"(a[0]), "r"(a[1]), "r"(a[2]), "r"(a[3]), "r"(b[0]), "r"(b[1]));
}

// ---------------- tf32 tensor-core dual GEMM --------------------------------
// grid.y: 0 -> support(half) = A@W ; 1 -> tmp(f32) = A@Wself + bias
// Optional BN(a,b)+ReLU fused into A-load.
__global__ __launch_bounds__(256, 2) void gemm_tc(
    const float* __restrict__ A,
    const float* __restrict__ W,
    const float* __restrict__ Wself,
    const float* __restrict__ bias,
    const float* __restrict__ bn_ab,    // null -> no BN on A
    __half2* __restrict__ suppH,
    float* __restrict__ outtmp)
{
    __shared__ float As[128 * 36];
    __shared__ float Bs[128 * 36];

    const int   by  = blockIdx.y;
    const float* B  = by ? Wself : W;
    const int m0   = blockIdx.x * 128;
    const int tid  = threadIdx.x;
    const int wid  = tid >> 5;
    const int lane = tid & 31;
    const int wy   = wid & 3;
    const int wx   = wid >> 2;
    const int g    = lane >> 2;
    const int tig  = lane & 3;

    float acc[2][8][4];
#pragma unroll
    for (int mt = 0; mt < 2; mt++)
#pragma unroll
        for (int nt = 0; nt < 8; nt++)
#pragma unroll
            for (int i = 0; i < 4; i++) acc[mt][nt][i] = 0.0f;

    for (int kc = 0; kc < DD; kc += 32) {
#pragma unroll
        for (int i = 0; i < 4; i++) {
            int idx = tid + i * 256;
            int row = idx >> 3;
            int kv  = (idx & 7) << 2;
            float4 v = make_float4(0.f, 0.f, 0.f, 0.f);
            int gr = m0 + row;
            if (gr < NN) v = *(const float4*)(A + (size_t)gr * DD + kc + kv);
            if (bn_ab) {
                float4 a4 = *(const float4*)(bn_ab + kc + kv);
                float4 b4 = *(const float4*)(bn_ab + DD + kc + kv);
                v.x = fmaxf(0.f, fmaf(v.x, a4.x, b4.x));
                v.y = fmaxf(0.f, fmaf(v.y, a4.y, b4.y));
                v.z = fmaxf(0.f, fmaf(v.z, a4.z, b4.z));
                v.w = fmaxf(0.f, fmaf(v.w, a4.w, b4.w));
            }
            float4 t;
            t.x = f2tf32(v.x); t.y = f2tf32(v.y);
            t.z = f2tf32(v.z); t.w = f2tf32(v.w);
            *(float4*)(&As[row * 36 + kv]) = t;
        }
#pragma unroll
        for (int i = 0; i < 4; i++) {
            int k  = lane;
            int n0 = ((tid >> 5) + i * 8) << 2;
            float4 v = *(const float4*)(B + (size_t)(kc + k) * DD + n0);
            Bs[(n0 + 0) * 36 + k] = f2tf32(v.x);
            Bs[(n0 + 1) * 36 + k] = f2tf32(v.y);
            Bs[(n0 + 2) * 36 + k] = f2tf32(v.z);
            Bs[(n0 + 3) * 36 + k] = f2tf32(v.w);
        }
        __syncthreads();

#pragma unroll
        for (int ks = 0; ks < 4; ks++) {
            int kk = ks * 8 + tig;
            uint32_t af[2][4];
#pragma unroll
            for (int mt = 0; mt < 2; mt++) {
                int rb = wy * 32 + mt * 16;
                af[mt][0] = __float_as_uint(As[(rb + g) * 36 + kk]);
                af[mt][1] = __float_as_uint(As[(rb + g + 8) * 36 + kk]);
                af[mt][2] = __float_as_uint(As[(rb + g) * 36 + kk + 4]);
                af[mt][3] = __float_as_uint(As[(rb + g + 8) * 36 + kk + 4]);
            }
            uint32_t bf[8][2];
#pragma unroll
            for (int nt = 0; nt < 8; nt++) {
                int n = wx * 64 + nt * 8 + g;
                bf[nt][0] = __float_as_uint(Bs[n * 36 + kk]);
                bf[nt][1] = __float_as_uint(Bs[n * 36 + kk + 4]);
            }
#pragma unroll
            for (int mt = 0; mt < 2; mt++)
#pragma unroll
                for (int nt = 0; nt < 8; nt++)
                    mma_tf32(acc[mt][nt], af[mt], bf[nt]);
        }
        __syncthreads();
    }

#pragma unroll
    for (int nt = 0; nt < 8; nt++) {
        int col = wx * 64 + nt * 8 + (tig << 1);
        float2 bb = make_float2(0.f, 0.f);
        if (by) bb = *(const float2*)(bias + col);
#pragma unroll
        for (int mt = 0; mt < 2; mt++) {
            int r0 = m0 + wy * 32 + mt * 16 + g;
            int r1 = r0 + 8;
            float2 v0 = make_float2(acc[mt][nt][0] + bb.x, acc[mt][nt][1] + bb.y);
            float2 v1 = make_float2(acc[mt][nt][2] + bb.x, acc[mt][nt][3] + bb.y);
            if (by) {
                if (r0 < NN) *(float2*)(outtmp + (size_t)r0 * DD + col) = v0;
                if (r1 < NN) *(float2*)(outtmp + (size_t)r1 * DD + col) = v1;
            } else {
                if (r0 < NN) suppH[(size_t)r0 * (DD / 2) + (col >> 1)] = __float22half2_rn(v0);
                if (r1 < NN) suppH[(size_t)r1 * (DD / 2) + (col >> 1)] = __float22half2_rn(v1);
            }
        }
    }
}

// ---------------- CSR build ---------------------------------------------------
__global__ __launch_bounds__(256) void histo(const int* __restrict__ rows)
{
    int e = blockIdx.x * blockDim.x + threadIdx.x;
    if (e < EADJ) atomicAdd(&g_counts[rows[e]], 1);
}

// single-pass decoupled-lookback exclusive scan of g_counts -> rowstart/cursor
__global__ __launch_bounds__(256) void scan_lookback()
{
    __shared__ int ws[8];
    __shared__ int s_prefix;
    const int bid = blockIdx.x;
    const int tid = threadIdx.x, lane = tid & 31, w = tid >> 5;
    int i = bid * 256 + tid;
    int v = (i < NN) ? g_counts[i] : 0;
    int inc = v;
#pragma unroll
    for (int o = 1; o < 32; o <<= 1) {
        int n = __shfl_up_sync(0xFFFFFFFFu, inc, o);
        if (lane >= o) inc += n;
    }
    if (lane == 31) ws[w] = inc;
    __syncthreads();
    if (w == 0 && lane < 8) {
        int s = ws[lane];
#pragma unroll
        for (int o = 1; o < 8; o <<= 1) {
            int n = __shfl_up_sync(0xFFu, s, o);
            if (lane >= o) s += n;
        }
        ws[lane] = s;
    }
    __syncthreads();
    int local_excl = (w ? ws[w - 1] : 0) + inc - v;
    int total = ws[7];

    if (tid == 0) {
        if (bid == 0) {
            g_scan_pref[0] = total;
            __threadfence();
            g_scan_flag[0] = 2;
            s_prefix = 0;
        } else {
            g_scan_agg[bid] = total;
            __threadfence();
            g_scan_flag[bid] = 1;
            // lookback
            int pref = 0;
            for (int j = bid - 1; j >= 0; j--) {
                int f;
                do { f = *(volatile int*)&g_scan_flag[j]; } while (f == 0);
                __threadfence();
                if (f == 2) { pref += *(volatile int*)&g_scan_pref[j]; break; }
                pref += *(volatile int*)&g_scan_agg[j];
            }
            g_scan_pref[bid] = pref + total;
            __threadfence();
            g_scan_flag[bid] = 2;
            s_prefix = pref;
        }
    }
    __syncthreads();
    int excl = s_prefix + local_excl;
    if (i < NN) { g_rowstart[i] = excl; g_cursor[i] = excl; }
    if (i == 0) g_rowstart[NN] = EADJ;
}

__global__ __launch_bounds__(256) void scatter_csr(
    const int* __restrict__ rows, const int* __restrict__ cols,
    const float* __restrict__ vals)
{
    int e = blockIdx.x * blockDim.x + threadIdx.x;
    if (e >= EADJ) return;
    int p = atomicAdd(&g_cursor[rows[e]], 1);
    g_csr[p] = make_int2(cols[e], __float_as_int(vals[e]));
}

// ---------------- CSR SpMM (half gather) + fused BN stats ---------------------
__global__ __launch_bounds__(256) void spmm_csr(
    const __half2* __restrict__ S2, float* __restrict__ Out,
    float* __restrict__ statpart)
{
    int lane = threadIdx.x & 31;
    int w    = threadIdx.x >> 5;
    int cg   = lane << 2;
    const int h2off = lane << 1;

    float4 s = make_float4(0.f, 0.f, 0.f, 0.f);
    float4 q = make_float4(0.f, 0.f, 0.f, 0.f);

#pragma unroll
    for (int r4 = 0; r4 < 4; r4++) {
        int row = blockIdx.x * 32 + w * 4 + r4;
        if (row >= NN) break;
        int e0 = g_rowstart[row];
        int e1 = g_rowstart[row + 1];
        float4 acc = make_float4(0.f, 0.f, 0.f, 0.f);
        int i = e0;
        for (; i + 4 <= e1; i += 4) {
            int2 cv0 = g_csr[i + 0];
            int2 cv1 = g_csr[i + 1];
            int2 cv2 = g_csr[i + 2];
            int2 cv3 = g_csr[i + 3];
            uint2 r0 = *(const uint2*)(S2 + (size_t)cv0.x * (DD / 2) + h2off);
            uint2 r1 = *(const uint2*)(S2 + (size_t)cv1.x * (DD / 2) + h2off);
            uint2 r2 = *(const uint2*)(S2 + (size_t)cv2.x * (DD / 2) + h2off);
            uint2 r3 = *(const uint2*)(S2 + (size_t)cv3.x * (DD / 2) + h2off);
            float v0 = __int_as_float(cv0.y), v1 = __int_as_float(cv1.y);
            float v2 = __int_as_float(cv2.y), v3 = __int_as_float(cv3.y);
            float2 a0 = __half22float2(*(__half2*)&r0.x), b0 = __half22float2(*(__half2*)&r0.y);
            float2 a1 = __half22float2(*(__half2*)&r1.x), b1 = __half22float2(*(__half2*)&r1.y);
            float2 a2 = __half22float2(*(__half2*)&r2.x), b2 = __half22float2(*(__half2*)&r2.y);
            float2 a3 = __half22float2(*(__half2*)&r3.x), b3 = __half22float2(*(__half2*)&r3.y);
            acc.x += v0 * a0.x + v1 * a1.x + v2 * a2.x + v3 * a3.x;
            acc.y += v0 * a0.y + v1 * a1.y + v2 * a2.y + v3 * a3.y;
            acc.z += v0 * b0.x + v1 * b1.x + v2 * b2.x + v3 * b3.x;
            acc.w += v0 * b0.y + v1 * b1.y + v2 * b2.y + v3 * b3.y;
        }
        for (; i < e1; i++) {
            int2 cv = g_csr[i];
            float vv = __int_as_float(cv.y);
            uint2 rr = *(const uint2*)(S2 + (size_t)cv.x * (DD / 2) + h2off);
            float2 aa = __half22float2(*(__half2*)&rr.x);
            float2 bb = __half22float2(*(__half2*)&rr.y);
            acc.x += vv * aa.x; acc.y += vv * aa.y;
            acc.z += vv * bb.x; acc.w += vv * bb.y;
        }
        float4* p = (float4*)(Out + (size_t)row * DD + cg);
        float4 t = *p;
        t.x += acc.x; t.y += acc.y; t.z += acc.z; t.w += acc.w;
        *p = t;
        s.x += t.x; s.y += t.y; s.z += t.z; s.w += t.w;
        q.x += t.x * t.x; q.y += t.y * t.y;
        q.z += t.z * t.z; q.w += t.w * t.w;
    }

    __shared__ float4 ss[8][32];
    __shared__ float4 qq[8][32];
    ss[w][lane] = s;
    qq[w][lane] = q;
    __syncthreads();
    if (w == 0) {
#pragma unroll
        for (int k = 1; k < 8; k++) {
            float4 a = ss[k][lane], b = qq[k][lane];
            s.x += a.x; s.y += a.y; s.z += a.z; s.w += a.w;
            q.x += b.x; q.y += b.y; q.z += b.z; q.w += b.w;
        }
        float* base = statpart + (size_t)(blockIdx.x & (NCOPY - 1)) * 2 * DD;
        atomicAdd((float4*)(base + cg), s);
        atomicAdd((float4*)(base + DD + cg), q);
    }
}

// fold NCOPY partials -> BN scale/shift: a = g*rsqrt(var+eps), b = be - m*a
__global__ __launch_bounds__(128) void reduce_stats(
    const float* __restrict__ statpart,
    const float* __restrict__ gm, const float* __restrict__ be,
    float* __restrict__ ab)
{
    int col = threadIdx.x;      // 0..127
    float s = 0.f, q = 0.f;
#pragma unroll
    for (int c = 0; c < NCOPY; c++) {
        s += statpart[c * 2 * DD + col];
        q += statpart[c * 2 * DD + DD + col];
    }
    const float invN = 1.0f / (float)NN;
    float m   = s * invN;
    float var = q * invN - m * m;
    float a   = gm[col] * rsqrtf(var + BNEPS);
    ab[col]      = a;
    ab[DD + col] = be[col] - m * a;
}

// ---------------- node scores (BN layer2 fused) -------------------------------
__global__ __launch_bounds__(256) void node_scores(
    const float* __restrict__ T2,
    const float* __restrict__ ab,
    const float* __restrict__ X,
    const float* __restrict__ Wc)
{
    int warp = (blockIdx.x * blockDim.x + threadIdx.x) >> 5;
    int lane = threadIdx.x & 31;
    if (warp >= NN) return;
    int cg = lane << 2;
    size_t off = (size_t)warp * DD + cg;
    float4 t = *(const float4*)(T2 + off);
    float4 x = *(const float4*)(X + off);
    float4 a4 = *(const float4*)(ab + cg);
    float4 b4 = *(const float4*)(ab + DD + cg);
    float h0 = fmaxf(0.f, fmaf(t.x, a4.x, b4.x)) + x.x;
    float h1 = fmaxf(0.f, fmaf(t.y, a4.y, b4.y)) + x.y;
    float h2 = fmaxf(0.f, fmaf(t.z, a4.z, b4.z)) + x.z;
    float h3 = fmaxf(0.f, fmaf(t.w, a4.w, b4.w)) + x.w;
    float4 w1 = *(const float4*)(Wc + cg);
    float4 w2 = *(const float4*)(Wc + DD + cg);
    float s1 = h0 * w1.x + h1 * w1.y + h2 * w1.z + h3 * w1.w;
    float s2 = h0 * w2.x + h1 * w2.y + h2 * w2.z + h3 * w2.w;
#pragma unroll
    for (int o = 16; o; o >>= 1) {
        s1 += __shfl_xor_sync(0xFFFFFFFFu, s1, o);
        s2 += __shfl_xor_sync(0xFFFFFFFFu, s2, o);
    }
    if (lane == 0) {
        g_s1[warp] = s1;
        g_s2[warp] = s2;
    }
}

// ---------------- edge prediction ---------------------------------------------
__global__ __launch_bounds__(256) void edge_pred(
    const int* __restrict__ ei,
    const float* __restrict__ bc,
    float* __restrict__ out)
{
    int e = blockIdx.x * blockDim.x + threadIdx.x;
    if (e >= EPRED) return;
    float z = g_s1[ei[e]] + g_s2[ei[e + EPRED]] + bc[0];
    out[e] = 1.0f / (1.0f + expf(-z));
}

// ---------------- launch ------------------------------------------------------
extern "C" void kernel_launch(void* const* d_in, const int* in_sizes, int n_in,
                              void* d_out, int out_size)
{
    const float* x       = (const float*)d_in[0];
    const int*   adj_row = (const int*)d_in[1];
    const int*   adj_col = (const int*)d_in[2];
    const float* adj_val = (const float*)d_in[3];
    const int*   eidx    = (const int*)d_in[4];
    const float* W       = (const float*)d_in[5];
    const float* Wself   = (const float*)d_in[6];
    const float* b       = (const float*)d_in[7];
    const float* gamma   = (const float*)d_in[8];
    const float* beta    = (const float*)d_in[9];
    const float* Wc      = (const float*)d_in[10];
    const float* bc      = (const float*)d_in[11];
    float* out           = (float*)d_out;

    __half2* suppH; float *tmp, *statpart, *bnab;
    int *counts, *flags;
    cudaGetSymbolAddress((void**)&suppH,    g_supp_h);
    cudaGetSymbolAddress((void**)&tmp,      g_tmp);
    cudaGetSymbolAddress((void**)&statpart, g_statpart);
    cudaGetSymbolAddress((void**)&bnab,     g_bnab);
    cudaGetSymbolAddress((void**)&counts,   g_counts);
    cudaGetSymbolAddress((void**)&flags,    g_scan_flag);

    const dim3 gemm_grid((NN + 127) / 128, 2);
    const int eb = (EADJ + 255) / 256;
    const int spmm_blocks = (NN + 31) / 32;

    // zero init (async memsets; graph-capturable)
    cudaMemsetAsync(counts, 0, NN * sizeof(int));
    cudaMemsetAsync(flags, 0, SCANB * sizeof(int));
    cudaMemsetAsync(statpart, 0, 2 * NCOPY * 2 * DD * sizeof(float));

    // CSR build
    histo<<<eb, 256>>>(adj_row);
    scan_lookback<<<SCANB, 256>>>();
    scatter_csr<<<eb, 256>>>(adj_row, adj_col, adj_val);

    // layer 1
    gemm_tc<<<gemm_grid, 256>>>(x, W, Wself, b, nullptr, suppH, tmp);
    spmm_csr<<<spmm_blocks, 256>>>(suppH, tmp, statpart);
    reduce_stats<<<1, 128>>>(statpart, gamma, beta, bnab);

    // layer 2 (BN+ReLU fused into A-load)
    gemm_tc<<<gemm_grid, 256>>>(tmp, W + DD * DD, Wself + DD * DD, b + DD,
                                bnab, suppH, tmp);
    spmm_csr<<<spmm_blocks, 256>>>(suppH, tmp, statpart + NCOPY * 2 * DD);
    reduce_stats<<<1, 128>>>(statpart + NCOPY * 2 * DD, gamma + DD, beta + DD,
                             bnab + 2 * DD);

    node_scores<<<(NN * 32 + 255) / 256, 256>>>(tmp, bnab + 2 * DD, x, Wc);
    edge_pred<<<(EPRED + 255) / 256, 256>>>(eidx, bc, out);
}

// round 7
// speedup vs baseline: 1.1345x; 1.1345x over previous
#include <cuda_runtime.h>
#include <cuda_fp16.h>
#include <math.h>
#include <stdint.h>

#define NN    50000
#define DD    128
#define EADJ  800000
#define EPRED 500000
#define BNEPS 1e-5f
#define SCANB 196          // ceil(NN/256)
#define NCOPY 32           // stat partial copies
#define GM    256          // GEMM CTA rows
#define AST   132          // smem row stride (floats): bank spacing 4

// ---------------- scratch ----------------------------------------------------
__device__ __half2 g_supp_h[NN * (DD / 2)];    // fp16 support
__device__ float g_tmp[NN * DD];
__device__ float g_statpart[2 * NCOPY * 2 * DD];
__device__ float g_bnab[2 * 2 * DD];           // [layer][a(128) | b(128)]
__device__ float g_s1[NN];
__device__ float g_s2[NN];
__device__ int   g_counts[NN];
__device__ int   g_rowstart[NN + 1];
__device__ int   g_cursor[NN];
__device__ int   g_scan_flag[SCANB];
__device__ int   g_scan_agg[SCANB];
__device__ int   g_scan_pref[SCANB];
__device__ int2  g_csr[EADJ];

// ---------------- helpers ----------------------------------------------------
__device__ __forceinline__ float f2tf32(float f) {
    uint32_t r;
    asm("cvt.rna.tf32.f32 %0, %1;" : "=r"(r) : "f"(f));
    return __uint_as_float(r);
}

__device__ __forceinline__ void mma_tf32(float* c, const uint32_t* a, const uint32_t* b) {
    asm volatile(
        "mma.sync.aligned.m16n8k8.row.col.f32.tf32.tf32.f32 "
        "{%0,%1,%2,%3}, {%4,%5,%6,%7}, {%8,%9}, {%0,%1,%2,%3};\n"
        : "+f"(c[0]), "+f"(c[1]), "+f"(c[2]), "+f"(c[3])
        : "r"(a[0]), "r"(a[1]), "r"(a[2]), "r"(a[3]), "r"(b[0]), "r"(b[1]));
}

// ---------------- tf32 tensor-core dual GEMM (full-K resident) ---------------
// CTA tile 256x128, 512 threads = 16 warps (4 wy x 4 wx), warp tile 64x32.
// All of A-tile (256x128) and B (128x128) staged in dynamic smem, one sync,
// 16 unrolled K-steps of m16n8k8. Stride 132 -> conflict-free LDS/STS.
// grid.y: 0 -> support(half) = A@W ; 1 -> tmp(f32) = A@Wself + bias
__global__ __launch_bounds__(512) void gemm_tc(
    const float* __restrict__ A,
    const float* __restrict__ W,
    const float* __restrict__ Wself,
    const float* __restrict__ bias,
    const float* __restrict__ bn_ab,    // null -> no BN on A
    __half2* __restrict__ suppH,
    float* __restrict__ outtmp)
{
    extern __shared__ float sm[];
    float* As = sm;                   // GM x AST
    float* Bs = sm + GM * AST;        // 128 x AST

    const int   by  = blockIdx.y;
    const float* B  = by ? Wself : W;
    const int m0   = blockIdx.x * GM;
    const int tid  = threadIdx.x;
    const int wid  = tid >> 5;
    const int lane = tid & 31;
    const int wy   = wid & 3;         // 64-row slice
    const int wx   = wid >> 2;        // 32-col slice
    const int g    = lane >> 2;
    const int tig  = lane & 3;

    // ---- stage A: 256 rows x 128 k (16 float4 per thread, coalesced) ----
#pragma unroll
    for (int i = 0; i < 16; i++) {
        int row = wid + i * 16;               // 0..255
        int kv  = lane << 2;                  // 0..124
        int gr  = m0 + row;
        float4 v = make_float4(0.f, 0.f, 0.f, 0.f);
        if (gr < NN) v = *(const float4*)(A + (size_t)gr * DD + kv);
        if (bn_ab) {
            float4 a4 = *(const float4*)(bn_ab + kv);
            float4 b4 = *(const float4*)(bn_ab + DD + kv);
            v.x = fmaxf(0.f, fmaf(v.x, a4.x, b4.x));
            v.y = fmaxf(0.f, fmaf(v.y, a4.y, b4.y));
            v.z = fmaxf(0.f, fmaf(v.z, a4.z, b4.z));
            v.w = fmaxf(0.f, fmaf(v.w, a4.w, b4.w));
        }
        float4 t;
        t.x = f2tf32(v.x); t.y = f2tf32(v.y);
        t.z = f2tf32(v.z); t.w = f2tf32(v.w);
        *(float4*)(&As[row * AST + kv]) = t;
    }
    // ---- stage B transposed: Bs[n][k]; 32 n-groups x 32 k-lanes x 4 kc ----
#pragma unroll
    for (int i = 0; i < 2; i++) {
        int k  = lane;                         // 0..31
        int n0 = (wid + i * 16) << 2;          // 0..124
#pragma unroll
        for (int kc = 0; kc < DD; kc += 32) {
            float4 v = *(const float4*)(B + (size_t)(kc + k) * DD + n0);
            Bs[(n0 + 0) * AST + kc + k] = f2tf32(v.x);
            Bs[(n0 + 1) * AST + kc + k] = f2tf32(v.y);
            Bs[(n0 + 2) * AST + kc + k] = f2tf32(v.z);
            Bs[(n0 + 3) * AST + kc + k] = f2tf32(v.w);
        }
    }
    __syncthreads();

    float acc[4][4][4];
#pragma unroll
    for (int mt = 0; mt < 4; mt++)
#pragma unroll
        for (int nt = 0; nt < 4; nt++)
#pragma unroll
            for (int i = 0; i < 4; i++) acc[mt][nt][i] = 0.0f;

#pragma unroll
    for (int ks = 0; ks < 16; ks++) {
        int kk = ks * 8 + tig;
        uint32_t af[4][4];
#pragma unroll
        for (int mt = 0; mt < 4; mt++) {
            int rb = wy * 64 + mt * 16;
            af[mt][0] = __float_as_uint(As[(rb + g) * AST + kk]);
            af[mt][1] = __float_as_uint(As[(rb + g + 8) * AST + kk]);
            af[mt][2] = __float_as_uint(As[(rb + g) * AST + kk + 4]);
            af[mt][3] = __float_as_uint(As[(rb + g + 8) * AST + kk + 4]);
        }
        uint32_t bf[4][2];
#pragma unroll
        for (int nt = 0; nt < 4; nt++) {
            int n = wx * 32 + nt * 8 + g;
            bf[nt][0] = __float_as_uint(Bs[n * AST + kk]);
            bf[nt][1] = __float_as_uint(Bs[n * AST + kk + 4]);
        }
#pragma unroll
        for (int mt = 0; mt < 4; mt++)
#pragma unroll
            for (int nt = 0; nt < 4; nt++)
                mma_tf32(acc[mt][nt], af[mt], bf[nt]);
    }

    // ---- epilogue ----
#pragma unroll
    for (int nt = 0; nt < 4; nt++) {
        int col = wx * 32 + nt * 8 + (tig << 1);
        float2 bb = make_float2(0.f, 0.f);
        if (by) bb = *(const float2*)(bias + col);
#pragma unroll
        for (int mt = 0; mt < 4; mt++) {
            int r0 = m0 + wy * 64 + mt * 16 + g;
            int r1 = r0 + 8;
            float2 v0 = make_float2(acc[mt][nt][0] + bb.x, acc[mt][nt][1] + bb.y);
            float2 v1 = make_float2(acc[mt][nt][2] + bb.x, acc[mt][nt][3] + bb.y);
            if (by) {
                if (r0 < NN) *(float2*)(outtmp + (size_t)r0 * DD + col) = v0;
                if (r1 < NN) *(float2*)(outtmp + (size_t)r1 * DD + col) = v1;
            } else {
                if (r0 < NN) suppH[(size_t)r0 * (DD / 2) + (col >> 1)] = __float22half2_rn(v0);
                if (r1 < NN) suppH[(size_t)r1 * (DD / 2) + (col >> 1)] = __float22half2_rn(v1);
            }
        }
    }
}

// ---------------- CSR build ---------------------------------------------------
__global__ __launch_bounds__(256) void histo(const int* __restrict__ rows)
{
    int e = blockIdx.x * blockDim.x + threadIdx.x;
    if (e < EADJ) atomicAdd(&g_counts[rows[e]], 1);
}

__global__ __launch_bounds__(256) void scan_lookback()
{
    __shared__ int ws[8];
    __shared__ int s_prefix;
    const int bid = blockIdx.x;
    const int tid = threadIdx.x, lane = tid & 31, w = tid >> 5;
    int i = bid * 256 + tid;
    int v = (i < NN) ? g_counts[i] : 0;
    int inc = v;
#pragma unroll
    for (int o = 1; o < 32; o <<= 1) {
        int n = __shfl_up_sync(0xFFFFFFFFu, inc, o);
        if (lane >= o) inc += n;
    }
    if (lane == 31) ws[w] = inc;
    __syncthreads();
    if (w == 0 && lane < 8) {
        int s = ws[lane];
#pragma unroll
        for (int o = 1; o < 8; o <<= 1) {
            int n = __shfl_up_sync(0xFFu, s, o);
            if (lane >= o) s += n;
        }
        ws[lane] = s;
    }
    __syncthreads();
    int local_excl = (w ? ws[w - 1] : 0) + inc - v;
    int total = ws[7];

    if (tid == 0) {
        if (bid == 0) {
            g_scan_pref[0] = total;
            __threadfence();
            g_scan_flag[0] = 2;
            s_prefix = 0;
        } else {
            g_scan_agg[bid] = total;
            __threadfence();
            g_scan_flag[bid] = 1;
            int pref = 0;
            for (int j = bid - 1; j >= 0; j--) {
                int f;
                do { f = *(volatile int*)&g_scan_flag[j]; } while (f == 0);
                __threadfence();
                if (f == 2) { pref += *(volatile int*)&g_scan_pref[j]; break; }
                pref += *(volatile int*)&g_scan_agg[j];
            }
            g_scan_pref[bid] = pref + total;
            __threadfence();
            g_scan_flag[bid] = 2;
            s_prefix = pref;
        }
    }
    __syncthreads();
    int excl = s_prefix + local_excl;
    if (i < NN) { g_rowstart[i] = excl; g_cursor[i] = excl; }
    if (i == 0) g_rowstart[NN] = EADJ;
}

__global__ __launch_bounds__(256) void scatter_csr(
    const int* __restrict__ rows, const int* __restrict__ cols,
    const float* __restrict__ vals)
{
    int e = blockIdx.x * blockDim.x + threadIdx.x;
    if (e >= EADJ) return;
    int p = atomicAdd(&g_cursor[rows[e]], 1);
    g_csr[p] = make_int2(cols[e], __float_as_int(vals[e]));
}

// ---------------- CSR SpMM (half gather, 1 row/warp) + fused BN stats --------
__global__ __launch_bounds__(256) void spmm_csr(
    const __half2* __restrict__ S2, float* __restrict__ Out,
    float* __restrict__ statpart)
{
    int lane = threadIdx.x & 31;
    int w    = threadIdx.x >> 5;
    int cg   = lane << 2;
    const int h2off = lane << 1;
    int row  = blockIdx.x * 8 + w;

    float4 s = make_float4(0.f, 0.f, 0.f, 0.f);
    float4 q = make_float4(0.f, 0.f, 0.f, 0.f);

    if (row < NN) {
        int e0 = g_rowstart[row];
        int e1 = g_rowstart[row + 1];
        float4 acc = make_float4(0.f, 0.f, 0.f, 0.f);
        int i = e0;
        for (; i + 4 <= e1; i += 4) {
            int2 cv0 = g_csr[i + 0];
            int2 cv1 = g_csr[i + 1];
            int2 cv2 = g_csr[i + 2];
            int2 cv3 = g_csr[i + 3];
            uint2 r0 = *(const uint2*)(S2 + (size_t)cv0.x * (DD / 2) + h2off);
            uint2 r1 = *(const uint2*)(S2 + (size_t)cv1.x * (DD / 2) + h2off);
            uint2 r2 = *(const uint2*)(S2 + (size_t)cv2.x * (DD / 2) + h2off);
            uint2 r3 = *(const uint2*)(S2 + (size_t)cv3.x * (DD / 2) + h2off);
            float v0 = __int_as_float(cv0.y), v1 = __int_as_float(cv1.y);
            float v2 = __int_as_float(cv2.y), v3 = __int_as_float(cv3.y);
            float2 a0 = __half22float2(*(__half2*)&r0.x), b0 = __half22float2(*(__half2*)&r0.y);
            float2 a1 = __half22float2(*(__half2*)&r1.x), b1 = __half22float2(*(__half2*)&r1.y);
            float2 a2 = __half22float2(*(__half2*)&r2.x), b2 = __half22float2(*(__half2*)&r2.y);
            float2 a3 = __half22float2(*(__half2*)&r3.x), b3 = __half22float2(*(__half2*)&r3.y);
            acc.x += v0 * a0.x + v1 * a1.x + v2 * a2.x + v3 * a3.x;
            acc.y += v0 * a0.y + v1 * a1.y + v2 * a2.y + v3 * a3.y;
            acc.z += v0 * b0.x + v1 * b1.x + v2 * b2.x + v3 * b3.x;
            acc.w += v0 * b0.y + v1 * b1.y + v2 * b2.y + v3 * b3.y;
        }
        for (; i < e1; i++) {
            int2 cv = g_csr[i];
            float vv = __int_as_float(cv.y);
            uint2 rr = *(const uint2*)(S2 + (size_t)cv.x * (DD / 2) + h2off);
            float2 aa = __half22float2(*(__half2*)&rr.x);
            float2 bb = __half22float2(*(__half2*)&rr.y);
            acc.x += vv * aa.x; acc.y += vv * aa.y;
            acc.z += vv * bb.x; acc.w += vv * bb.y;
        }
        float4* p = (float4*)(Out + (size_t)row * DD + cg);
        float4 t = *p;
        t.x += acc.x; t.y += acc.y; t.z += acc.z; t.w += acc.w;
        *p = t;
        s = t;
        q.x = t.x * t.x; q.y = t.y * t.y;
        q.z = t.z * t.z; q.w = t.w * t.w;
    }

    __shared__ float4 ss[8][32];
    __shared__ float4 qq[8][32];
    ss[w][lane] = s;
    qq[w][lane] = q;
    __syncthreads();
    if (w == 0) {
#pragma unroll
        for (int k = 1; k < 8; k++) {
            float4 a = ss[k][lane], b = qq[k][lane];
            s.x += a.x; s.y += a.y; s.z += a.z; s.w += a.w;
            q.x += b.x; q.y += b.y; q.z += b.z; q.w += b.w;
        }
        float* base = statpart + (size_t)(blockIdx.x & (NCOPY - 1)) * 2 * DD;
        atomicAdd((float4*)(base + cg), s);
        atomicAdd((float4*)(base + DD + cg), q);
    }
}

// fold NCOPY partials -> BN scale/shift
__global__ __launch_bounds__(128) void reduce_stats(
    const float* __restrict__ statpart,
    const float* __restrict__ gm, const float* __restrict__ be,
    float* __restrict__ ab)
{
    int col = threadIdx.x;
    float s = 0.f, q = 0.f;
#pragma unroll
    for (int c = 0; c < NCOPY; c++) {
        s += statpart[c * 2 * DD + col];
        q += statpart[c * 2 * DD + DD + col];
    }
    const float invN = 1.0f / (float)NN;
    float m   = s * invN;
    float var = q * invN - m * m;
    float a   = gm[col] * rsqrtf(var + BNEPS);
    ab[col]      = a;
    ab[DD + col] = be[col] - m * a;
}

// ---------------- node scores (BN layer2 fused) -------------------------------
__global__ __launch_bounds__(256) void node_scores(
    const float* __restrict__ T2,
    const float* __restrict__ ab,
    const float* __restrict__ X,
    const float* __restrict__ Wc)
{
    int warp = (blockIdx.x * blockDim.x + threadIdx.x) >> 5;
    int lane = threadIdx.x & 31;
    if (warp >= NN) return;
    int cg = lane << 2;
    size_t off = (size_t)warp * DD + cg;
    float4 t = *(const float4*)(T2 + off);
    float4 x = *(const float4*)(X + off);
    float4 a4 = *(const float4*)(ab + cg);
    float4 b4 = *(const float4*)(ab + DD + cg);
    float h0 = fmaxf(0.f, fmaf(t.x, a4.x, b4.x)) + x.x;
    float h1 = fmaxf(0.f, fmaf(t.y, a4.y, b4.y)) + x.y;
    float h2 = fmaxf(0.f, fmaf(t.z, a4.z, b4.z)) + x.z;
    float h3 = fmaxf(0.f, fmaf(t.w, a4.w, b4.w)) + x.w;
    float4 w1 = *(const float4*)(Wc + cg);
    float4 w2 = *(const float4*)(Wc + DD + cg);
    float s1 = h0 * w1.x + h1 * w1.y + h2 * w1.z + h3 * w1.w;
    float s2 = h0 * w2.x + h1 * w2.y + h2 * w2.z + h3 * w2.w;
#pragma unroll
    for (int o = 16; o; o >>= 1) {
        s1 += __shfl_xor_sync(0xFFFFFFFFu, s1, o);
        s2 += __shfl_xor_sync(0xFFFFFFFFu, s2, o);
    }
    if (lane == 0) {
        g_s1[warp] = s1;
        g_s2[warp] = s2;
    }
}

// ---------------- edge prediction ---------------------------------------------
__global__ __launch_bounds__(256) void edge_pred(
    const int* __restrict__ ei,
    const float* __restrict__ bc,
    float* __restrict__ out)
{
    int e = blockIdx.x * blockDim.x + threadIdx.x;
    if (e >= EPRED) return;
    float z = g_s1[ei[e]] + g_s2[ei[e + EPRED]] + bc[0];
    out[e] = 1.0f / (1.0f + expf(-z));
}

// ---------------- launch ------------------------------------------------------
extern "C" void kernel_launch(void* const* d_in, const int* in_sizes, int n_in,
                              void* d_out, int out_size)
{
    const float* x       = (const float*)d_in[0];
    const int*   adj_row = (const int*)d_in[1];
    const int*   adj_col = (const int*)d_in[2];
    const float* adj_val = (const float*)d_in[3];
    const int*   eidx    = (const int*)d_in[4];
    const float* W       = (const float*)d_in[5];
    const float* Wself   = (const float*)d_in[6];
    const float* b       = (const float*)d_in[7];
    const float* gamma   = (const float*)d_in[8];
    const float* beta    = (const float*)d_in[9];
    const float* Wc      = (const float*)d_in[10];
    const float* bc      = (const float*)d_in[11];
    float* out           = (float*)d_out;

    __half2* suppH; float *tmp, *statpart, *bnab;
    int *counts, *flags;
    cudaGetSymbolAddress((void**)&suppH,    g_supp_h);
    cudaGetSymbolAddress((void**)&tmp,      g_tmp);
    cudaGetSymbolAddress((void**)&statpart, g_statpart);
    cudaGetSymbolAddress((void**)&bnab,     g_bnab);
    cudaGetSymbolAddress((void**)&counts,   g_counts);
    cudaGetSymbolAddress((void**)&flags,    g_scan_flag);

    const int gemm_smem = (GM * AST + DD * AST) * (int)sizeof(float);
    cudaFuncSetAttribute(gemm_tc, cudaFuncAttributeMaxDynamicSharedMemorySize,
                         gemm_smem);

    const dim3 gemm_grid((NN + GM - 1) / GM, 2);
    const int eb = (EADJ + 255) / 256;
    const int spmm_blocks = (NN + 7) / 8;

    cudaMemsetAsync(counts, 0, NN * sizeof(int));
    cudaMemsetAsync(flags, 0, SCANB * sizeof(int));
    cudaMemsetAsync(statpart, 0, 2 * NCOPY * 2 * DD * sizeof(float));

    // CSR build
    histo<<<eb, 256>>>(adj_row);
    scan_lookback<<<SCANB, 256>>>();
    scatter_csr<<<eb, 256>>>(adj_row, adj_col, adj_val);

    // layer 1
    gemm_tc<<<gemm_grid, 512, gemm_smem>>>(x, W, Wself, b, nullptr, suppH, tmp);
    spmm_csr<<<spmm_blocks, 256>>>(suppH, tmp, statpart);
    reduce_stats<<<1, 128>>>(statpart, gamma, beta, bnab);

    // layer 2 (BN+ReLU fused into A-load)
    gemm_tc<<<gemm_grid, 512, gemm_smem>>>(tmp, W + DD * DD, Wself + DD * DD,
                                           b + DD, bnab, suppH, tmp);
    spmm_csr<<<spmm_blocks, 256>>>(suppH, tmp, statpart + NCOPY * 2 * DD);
    reduce_stats<<<1, 128>>>(statpart + NCOPY * 2 * DD, gamma + DD, beta + DD,
                             bnab + 2 * DD);

    node_scores<<<(NN * 32 + 255) / 256, 256>>>(tmp, bnab + 2 * DD, x, Wc);
    edge_pred<<<(EPRED + 255) / 256, 256>>>(eidx, bc, out);
}

// round 8
// speedup vs baseline: 1.1819x; 1.0417x over previous
#include <cuda_runtime.h>
#include <cuda_fp16.h>
#include <math.h>
#include <stdint.h>

#define NN    50000
#define DD    128
#define EADJ  800000
#define EPRED 500000
#define BNEPS 1e-5f
#define SCANB 196          // ceil(NN/256)
#define NCOPY 32           // stat partial copies
#define AST   132          // smem row stride (floats)
#define TILES 391          // ceil(NN/128)
#define GEMX  74           // persistent CTAs per matrix (74*2 = 148 = 1 wave)

// ---------------- scratch ----------------------------------------------------
__device__ __half2 g_supp_h[NN * (DD / 2)];    // fp16 support
__device__ float g_tmp[NN * DD];
__device__ float g_statpart[2 * NCOPY * 2 * DD];
__device__ float g_bnab[2 * 2 * DD];           // [layer][a(128) | b(128)]
__device__ float g_s1[NN];
__device__ float g_s2[NN];
__device__ int   g_counts[NN];
__device__ int   g_rowstart[NN + 1];
__device__ int   g_cursor[NN];
__device__ int   g_scan_flag[SCANB];
__device__ int   g_scan_agg[SCANB];
__device__ int   g_scan_pref[SCANB];
__device__ int2  g_csr[EADJ];

// ---------------- helpers ----------------------------------------------------
__device__ __forceinline__ float f2tf32(float f) {
    uint32_t r;
    asm("cvt.rna.tf32.f32 %0, %1;" : "=r"(r) : "f"(f));
    return __uint_as_float(r);
}

__device__ __forceinline__ void mma_tf32(float* c, const uint32_t* a, const uint32_t* b) {
    asm volatile(
        "mma.sync.aligned.m16n8k8.row.col.f32.tf32.tf32.f32 "
        "{%0,%1,%2,%3}, {%4,%5,%6,%7}, {%8,%9}, {%0,%1,%2,%3};\n"
        : "+f"(c[0]), "+f"(c[1]), "+f"(c[2]), "+f"(c[3])
        : "r"(a[0]), "r"(a[1]), "r"(a[2]), "r"(a[3]), "r"(b[0]), "r"(b[1]));
}

// ---------------- persistent tf32 GEMM ---------------------------------------
// grid (GEMX, 2): by picks W (-> support, half) or Wself (-> tmp + bias).
// Each CTA: stage its B matrix once (converted, transposed Bs[n][k]); then loop
// over row tiles t = bx, bx+GEMX, ... : prefetch next tile's A into registers,
// compute current tile from smem, write epilogue, convert+store next tile.
// 512 threads = 16 warps, warp tile 32x32 (wy 4 x wx 4). One sync per tile.
__global__ __launch_bounds__(512) void gemm_persist(
    const float* __restrict__ A,
    const float* __restrict__ W,
    const float* __restrict__ Wself,
    const float* __restrict__ bias,
    const float* __restrict__ bn_ab,    // null -> no BN on A
    __half2* __restrict__ suppH,
    float* __restrict__ outtmp)
{
    extern __shared__ float sm[];
    float* Bs  = sm;                    // 128 x AST
    float* As0 = sm + DD * AST;         // 128 x AST
    float* As1 = As0 + DD * AST;        // 128 x AST

    const int   by  = blockIdx.y;
    const float* B  = by ? Wself : W;
    const int tid  = threadIdx.x;
    const int wid  = tid >> 5;
    const int lane = tid & 31;
    const int wy   = wid & 3;           // 32-row slice
    const int wx   = wid >> 2;          // 32-col slice
    const int g    = lane >> 2;
    const int tig  = lane & 3;

    // per-thread A staging map: 8 float4; idx = tid + p*512
    // row = idx>>5 (0..127), c4 = idx&31 (float4 within row)
    // ---- stage B once: Bs[n][k] transposed + converted ----
#pragma unroll
    for (int i = 0; i < 2; i++) {
        int k  = lane;                          // 0..31
        int n0 = (wid + i * 16) << 2;           // 0..124
#pragma unroll
        for (int kc = 0; kc < DD; kc += 32) {
            float4 v = *(const float4*)(B + (size_t)(kc + k) * DD + n0);
            Bs[(n0 + 0) * AST + kc + k] = f2tf32(v.x);
            Bs[(n0 + 1) * AST + kc + k] = f2tf32(v.y);
            Bs[(n0 + 2) * AST + kc + k] = f2tf32(v.z);
            Bs[(n0 + 3) * AST + kc + k] = f2tf32(v.w);
        }
    }

    // bias fragment (by=1 only), per warp column range
    float2 bb[4];
#pragma unroll
    for (int nt = 0; nt < 4; nt++) {
        int col = wx * 32 + nt * 8 + (tig << 1);
        bb[nt] = by ? *(const float2*)(bias + col) : make_float2(0.f, 0.f);
    }

    float4 pf[8];
    const int t0 = blockIdx.x;

    // prefetch + stage tile 0
#pragma unroll
    for (int p = 0; p < 8; p++) {
        int idx = tid + p * 512;
        int row = idx >> 5, c4 = idx & 31;
        int gr  = t0 * 128 + row;
        pf[p] = (gr < NN) ? *(const float4*)(A + (size_t)gr * DD + (c4 << 2))
                          : make_float4(0.f, 0.f, 0.f, 0.f);
    }
#pragma unroll
    for (int p = 0; p < 8; p++) {
        int idx = tid + p * 512;
        int row = idx >> 5, c4 = idx & 31;
        int kv  = c4 << 2;
        float4 v = pf[p];
        if (bn_ab) {
            float4 a4 = *(const float4*)(bn_ab + kv);
            float4 b4 = *(const float4*)(bn_ab + DD + kv);
            v.x = fmaxf(0.f, fmaf(v.x, a4.x, b4.x));
            v.y = fmaxf(0.f, fmaf(v.y, a4.y, b4.y));
            v.z = fmaxf(0.f, fmaf(v.z, a4.z, b4.z));
            v.w = fmaxf(0.f, fmaf(v.w, a4.w, b4.w));
        }
        float4 t4;
        t4.x = f2tf32(v.x); t4.y = f2tf32(v.y);
        t4.z = f2tf32(v.z); t4.w = f2tf32(v.w);
        *(float4*)(&As0[row * AST + kv]) = t4;
    }
    __syncthreads();

    float* cur = As0;
    float* nxt = As1;

    for (int t = t0; t < TILES; t += GEMX) {
        const int tn = t + GEMX;
        // ---- prefetch next tile's A into registers (overlaps compute) ----
        if (tn < TILES) {
#pragma unroll
            for (int p = 0; p < 8; p++) {
                int idx = tid + p * 512;
                int row = idx >> 5, c4 = idx & 31;
                int gr  = tn * 128 + row;
                pf[p] = (gr < NN) ? *(const float4*)(A + (size_t)gr * DD + (c4 << 2))
                                  : make_float4(0.f, 0.f, 0.f, 0.f);
            }
        }

        // ---- compute 128x128 tile ----
        float acc[2][4][4];
#pragma unroll
        for (int mt = 0; mt < 2; mt++)
#pragma unroll
            for (int nt = 0; nt < 4; nt++)
#pragma unroll
                for (int i = 0; i < 4; i++) acc[mt][nt][i] = 0.0f;

#pragma unroll
        for (int ks = 0; ks < 16; ks++) {
            int kk = ks * 8 + tig;
            uint32_t af[2][4];
#pragma unroll
            for (int mt = 0; mt < 2; mt++) {
                int rb = wy * 32 + mt * 16;
                af[mt][0] = __float_as_uint(cur[(rb + g) * AST + kk]);
                af[mt][1] = __float_as_uint(cur[(rb + g + 8) * AST + kk]);
                af[mt][2] = __float_as_uint(cur[(rb + g) * AST + kk + 4]);
                af[mt][3] = __float_as_uint(cur[(rb + g + 8) * AST + kk + 4]);
            }
            uint32_t bf[4][2];
#pragma unroll
            for (int nt = 0; nt < 4; nt++) {
                int n = wx * 32 + nt * 8 + g;
                bf[nt][0] = __float_as_uint(Bs[n * AST + kk]);
                bf[nt][1] = __float_as_uint(Bs[n * AST + kk + 4]);
            }
#pragma unroll
            for (int mt = 0; mt < 2; mt++)
#pragma unroll
                for (int nt = 0; nt < 4; nt++)
                    mma_tf32(acc[mt][nt], af[mt], bf[nt]);
        }

        // ---- epilogue for tile t ----
        const int m0 = t * 128;
#pragma unroll
        for (int nt = 0; nt < 4; nt++) {
            int col = wx * 32 + nt * 8 + (tig << 1);
#pragma unroll
            for (int mt = 0; mt < 2; mt++) {
                int r0 = m0 + wy * 32 + mt * 16 + g;
                int r1 = r0 + 8;
                float2 v0 = make_float2(acc[mt][nt][0] + bb[nt].x, acc[mt][nt][1] + bb[nt].y);
                float2 v1 = make_float2(acc[mt][nt][2] + bb[nt].x, acc[mt][nt][3] + bb[nt].y);
                if (by) {
                    if (r0 < NN) *(float2*)(outtmp + (size_t)r0 * DD + col) = v0;
                    if (r1 < NN) *(float2*)(outtmp + (size_t)r1 * DD + col) = v1;
                } else {
                    if (r0 < NN) suppH[(size_t)r0 * (DD / 2) + (col >> 1)] = __float22half2_rn(v0);
                    if (r1 < NN) suppH[(size_t)r1 * (DD / 2) + (col >> 1)] = __float22half2_rn(v1);
                }
            }
        }

        // ---- convert + store next tile into the spare buffer ----
        if (tn < TILES) {
#pragma unroll
            for (int p = 0; p < 8; p++) {
                int idx = tid + p * 512;
                int row = idx >> 5, c4 = idx & 31;
                int kv  = c4 << 2;
                float4 v = pf[p];
                if (bn_ab) {
                    float4 a4 = *(const float4*)(bn_ab + kv);
                    float4 b4 = *(const float4*)(bn_ab + DD + kv);
                    v.x = fmaxf(0.f, fmaf(v.x, a4.x, b4.x));
                    v.y = fmaxf(0.f, fmaf(v.y, a4.y, b4.y));
                    v.z = fmaxf(0.f, fmaf(v.z, a4.z, b4.z));
                    v.w = fmaxf(0.f, fmaf(v.w, a4.w, b4.w));
                }
                float4 t4;
                t4.x = f2tf32(v.x); t4.y = f2tf32(v.y);
                t4.z = f2tf32(v.z); t4.w = f2tf32(v.w);
                *(float4*)(&nxt[row * AST + kv]) = t4;
            }
        }
        __syncthreads();
        float* tmpp = cur; cur = nxt; nxt = tmpp;
    }
}

// ---------------- CSR build ---------------------------------------------------
__global__ __launch_bounds__(256) void histo(const int* __restrict__ rows)
{
    int e = blockIdx.x * blockDim.x + threadIdx.x;
    if (e < EADJ) atomicAdd(&g_counts[rows[e]], 1);
}

__global__ __launch_bounds__(256) void scan_lookback()
{
    __shared__ int ws[8];
    __shared__ int s_prefix;
    const int bid = blockIdx.x;
    const int tid = threadIdx.x, lane = tid & 31, w = tid >> 5;
    int i = bid * 256 + tid;
    int v = (i < NN) ? g_counts[i] : 0;
    int inc = v;
#pragma unroll
    for (int o = 1; o < 32; o <<= 1) {
        int n = __shfl_up_sync(0xFFFFFFFFu, inc, o);
        if (lane >= o) inc += n;
    }
    if (lane == 31) ws[w] = inc;
    __syncthreads();
    if (w == 0 && lane < 8) {
        int s = ws[lane];
#pragma unroll
        for (int o = 1; o < 8; o <<= 1) {
            int n = __shfl_up_sync(0xFFu, s, o);
            if (lane >= o) s += n;
        }
        ws[lane] = s;
    }
    __syncthreads();
    int local_excl = (w ? ws[w - 1] : 0) + inc - v;
    int total = ws[7];

    if (tid == 0) {
        if (bid == 0) {
            g_scan_pref[0] = total;
            __threadfence();
            g_scan_flag[0] = 2;
            s_prefix = 0;
        } else {
            g_scan_agg[bid] = total;
            __threadfence();
            g_scan_flag[bid] = 1;
            int pref = 0;
            for (int j = bid - 1; j >= 0; j--) {
                int f;
                do { f = *(volatile int*)&g_scan_flag[j]; } while (f == 0);
                __threadfence();
                if (f == 2) { pref += *(volatile int*)&g_scan_pref[j]; break; }
                pref += *(volatile int*)&g_scan_agg[j];
            }
            g_scan_pref[bid] = pref + total;
            __threadfence();
            g_scan_flag[bid] = 2;
            s_prefix = pref;
        }
    }
    __syncthreads();
    int excl = s_prefix + local_excl;
    if (i < NN) { g_rowstart[i] = excl; g_cursor[i] = excl; }
    if (i == 0) g_rowstart[NN] = EADJ;
}

__global__ __launch_bounds__(256) void scatter_csr(
    const int* __restrict__ rows, const int* __restrict__ cols,
    const float* __restrict__ vals)
{
    int e = blockIdx.x * blockDim.x + threadIdx.x;
    if (e >= EADJ) return;
    int p = atomicAdd(&g_cursor[rows[e]], 1);
    g_csr[p] = make_int2(cols[e], __float_as_int(vals[e]));
}

// ---------------- CSR SpMM (half gather, 1 row/warp) + fused BN stats --------
__global__ __launch_bounds__(256) void spmm_csr(
    const __half2* __restrict__ S2, float* __restrict__ Out,
    float* __restrict__ statpart)
{
    int lane = threadIdx.x & 31;
    int w    = threadIdx.x >> 5;
    int cg   = lane << 2;
    const int h2off = lane << 1;
    int row  = blockIdx.x * 8 + w;

    float4 s = make_float4(0.f, 0.f, 0.f, 0.f);
    float4 q = make_float4(0.f, 0.f, 0.f, 0.f);

    if (row < NN) {
        int e0 = g_rowstart[row];
        int e1 = g_rowstart[row + 1];
        float4 acc = make_float4(0.f, 0.f, 0.f, 0.f);
        int i = e0;
        for (; i + 4 <= e1; i += 4) {
            int2 cv0 = g_csr[i + 0];
            int2 cv1 = g_csr[i + 1];
            int2 cv2 = g_csr[i + 2];
            int2 cv3 = g_csr[i + 3];
            uint2 r0 = *(const uint2*)(S2 + (size_t)cv0.x * (DD / 2) + h2off);
            uint2 r1 = *(const uint2*)(S2 + (size_t)cv1.x * (DD / 2) + h2off);
            uint2 r2 = *(const uint2*)(S2 + (size_t)cv2.x * (DD / 2) + h2off);
            uint2 r3 = *(const uint2*)(S2 + (size_t)cv3.x * (DD / 2) + h2off);
            float v0 = __int_as_float(cv0.y), v1 = __int_as_float(cv1.y);
            float v2 = __int_as_float(cv2.y), v3 = __int_as_float(cv3.y);
            float2 a0 = __half22float2(*(__half2*)&r0.x), b0 = __half22float2(*(__half2*)&r0.y);
            float2 a1 = __half22float2(*(__half2*)&r1.x), b1 = __half22float2(*(__half2*)&r1.y);
            float2 a2 = __half22float2(*(__half2*)&r2.x), b2 = __half22float2(*(__half2*)&r2.y);
            float2 a3 = __half22float2(*(__half2*)&r3.x), b3 = __half22float2(*(__half2*)&r3.y);
            acc.x += v0 * a0.x + v1 * a1.x + v2 * a2.x + v3 * a3.x;
            acc.y += v0 * a0.y + v1 * a1.y + v2 * a2.y + v3 * a3.y;
            acc.z += v0 * b0.x + v1 * b1.x + v2 * b2.x + v3 * b3.x;
            acc.w += v0 * b0.y + v1 * b1.y + v2 * b2.y + v3 * b3.y;
        }
        for (; i < e1; i++) {
            int2 cv = g_csr[i];
            float vv = __int_as_float(cv.y);
            uint2 rr = *(const uint2*)(S2 + (size_t)cv.x * (DD / 2) + h2off);
            float2 aa = __half22float2(*(__half2*)&rr.x);
            float2 bbv = __half22float2(*(__half2*)&rr.y);
            acc.x += vv * aa.x; acc.y += vv * aa.y;
            acc.z += vv * bbv.x; acc.w += vv * bbv.y;
        }
        float4* p = (float4*)(Out + (size_t)row * DD + cg);
        float4 t = *p;
        t.x += acc.x; t.y += acc.y; t.z += acc.z; t.w += acc.w;
        *p = t;
        s = t;
        q.x = t.x * t.x; q.y = t.y * t.y;
        q.z = t.z * t.z; q.w = t.w * t.w;
    }

    __shared__ float4 ss[8][32];
    __shared__ float4 qq[8][32];
    ss[w][lane] = s;
    qq[w][lane] = q;
    __syncthreads();
    if (w == 0) {
#pragma unroll
        for (int k = 1; k < 8; k++) {
            float4 a = ss[k][lane], b = qq[k][lane];
            s.x += a.x; s.y += a.y; s.z += a.z; s.w += a.w;
            q.x += b.x; q.y += b.y; q.z += b.z; q.w += b.w;
        }
        float* base = statpart + (size_t)(blockIdx.x & (NCOPY - 1)) * 2 * DD;
        atomicAdd((float4*)(base + cg), s);
        atomicAdd((float4*)(base + DD + cg), q);
    }
}

// fold NCOPY partials -> BN scale/shift
__global__ __launch_bounds__(128) void reduce_stats(
    const float* __restrict__ statpart,
    const float* __restrict__ gm, const float* __restrict__ be,
    float* __restrict__ ab)
{
    int col = threadIdx.x;
    float s = 0.f, q = 0.f;
#pragma unroll
    for (int c = 0; c < NCOPY; c++) {
        s += statpart[c * 2 * DD + col];
        q += statpart[c * 2 * DD + DD + col];
    }
    const float invN = 1.0f / (float)NN;
    float m   = s * invN;
    float var = q * invN - m * m;
    float a   = gm[col] * rsqrtf(var + BNEPS);
    ab[col]      = a;
    ab[DD + col] = be[col] - m * a;
}

// ---------------- node scores (BN layer2 fused) -------------------------------
__global__ __launch_bounds__(256) void node_scores(
    const float* __restrict__ T2,
    const float* __restrict__ ab,
    const float* __restrict__ X,
    const float* __restrict__ Wc)
{
    int warp = (blockIdx.x * blockDim.x + threadIdx.x) >> 5;
    int lane = threadIdx.x & 31;
    if (warp >= NN) return;
    int cg = lane << 2;
    size_t off = (size_t)warp * DD + cg;
    float4 t = *(const float4*)(T2 + off);
    float4 x = *(const float4*)(X + off);
    float4 a4 = *(const float4*)(ab + cg);
    float4 b4 = *(const float4*)(ab + DD + cg);
    float h0 = fmaxf(0.f, fmaf(t.x, a4.x, b4.x)) + x.x;
    float h1 = fmaxf(0.f, fmaf(t.y, a4.y, b4.y)) + x.y;
    float h2 = fmaxf(0.f, fmaf(t.z, a4.z, b4.z)) + x.z;
    float h3 = fmaxf(0.f, fmaf(t.w, a4.w, b4.w)) + x.w;
    float4 w1 = *(const float4*)(Wc + cg);
    float4 w2 = *(const float4*)(Wc + DD + cg);
    float s1 = h0 * w1.x + h1 * w1.y + h2 * w1.z + h3 * w1.w;
    float s2 = h0 * w2.x + h1 * w2.y + h2 * w2.z + h3 * w2.w;
#pragma unroll
    for (int o = 16; o; o >>= 1) {
        s1 += __shfl_xor_sync(0xFFFFFFFFu, s1, o);
        s2 += __shfl_xor_sync(0xFFFFFFFFu, s2, o);
    }
    if (lane == 0) {
        g_s1[warp] = s1;
        g_s2[warp] = s2;
    }
}

// ---------------- edge prediction ---------------------------------------------
__global__ __launch_bounds__(256) void edge_pred(
    const int* __restrict__ ei,
    const float* __restrict__ bc,
    float* __restrict__ out)
{
    int e = blockIdx.x * blockDim.x + threadIdx.x;
    if (e >= EPRED) return;
    float z = g_s1[ei[e]] + g_s2[ei[e + EPRED]] + bc[0];
    out[e] = 1.0f / (1.0f + expf(-z));
}

// ---------------- launch ------------------------------------------------------
extern "C" void kernel_launch(void* const* d_in, const int* in_sizes, int n_in,
                              void* d_out, int out_size)
{
    const float* x       = (const float*)d_in[0];
    const int*   adj_row = (const int*)d_in[1];
    const int*   adj_col = (const int*)d_in[2];
    const float* adj_val = (const float*)d_in[3];
    const int*   eidx    = (const int*)d_in[4];
    const float* W       = (const float*)d_in[5];
    const float* Wself   = (const float*)d_in[6];
    const float* b       = (const float*)d_in[7];
    const float* gamma   = (const float*)d_in[8];
    const float* beta    = (const float*)d_in[9];
    const float* Wc      = (const float*)d_in[10];
    const float* bc      = (const float*)d_in[11];
    float* out           = (float*)d_out;

    __half2* suppH; float *tmp, *statpart, *bnab;
    int *counts, *flags;
    cudaGetSymbolAddress((void**)&suppH,    g_supp_h);
    cudaGetSymbolAddress((void**)&tmp,      g_tmp);
    cudaGetSymbolAddress((void**)&statpart, g_statpart);
    cudaGetSymbolAddress((void**)&bnab,     g_bnab);
    cudaGetSymbolAddress((void**)&counts,   g_counts);
    cudaGetSymbolAddress((void**)&flags,    g_scan_flag);

    const int gemm_smem = 3 * DD * AST * (int)sizeof(float);   // B + 2 A bufs
    cudaFuncSetAttribute(gemm_persist,
                         cudaFuncAttributeMaxDynamicSharedMemorySize, gemm_smem);

    const dim3 gemm_grid(GEMX, 2);
    const int eb = (EADJ + 255) / 256;
    const int spmm_blocks = (NN + 7) / 8;

    cudaMemsetAsync(counts, 0, NN * sizeof(int));
    cudaMemsetAsync(flags, 0, SCANB * sizeof(int));
    cudaMemsetAsync(statpart, 0, 2 * NCOPY * 2 * DD * sizeof(float));

    // CSR build
    histo<<<eb, 256>>>(adj_row);
    scan_lookback<<<SCANB, 256>>>();
    scatter_csr<<<eb, 256>>>(adj_row, adj_col, adj_val);

    // layer 1
    gemm_persist<<<gemm_grid, 512, gemm_smem>>>(x, W, Wself, b, nullptr,
                                                suppH, tmp);
    spmm_csr<<<spmm_blocks, 256>>>(suppH, tmp, statpart);
    reduce_stats<<<1, 128>>>(statpart, gamma, beta, bnab);

    // layer 2 (BN+ReLU fused into A staging)
    gemm_persist<<<gemm_grid, 512, gemm_smem>>>(tmp, W + DD * DD,
                                                Wself + DD * DD, b + DD,
                                                bnab, suppH, tmp);
    spmm_csr<<<spmm_blocks, 256>>>(suppH, tmp, statpart + NCOPY * 2 * DD);
    reduce_stats<<<1, 128>>>(statpart + NCOPY * 2 * DD, gamma + DD, beta + DD,
                             bnab + 2 * DD);

    node_scores<<<(NN * 32 + 255) / 256, 256>>>(tmp, bnab + 2 * DD, x, Wc);
    edge_pred<<<(EPRED + 255) / 256, 256>>>(eidx, bc, out);
}

// round 9
// speedup vs baseline: 1.1926x; 1.0091x over previous
#include <cuda_runtime.h>
#include <cuda_fp16.h>
#include <math.h>
#include <stdint.h>

#define NN    50000
#define DD    128
#define EADJ  800000
#define EPRED 500000
#define BNEPS 1e-5f
#define SCANB 196          // ceil(NN/256)
#define NCOPY 32           // stat partial copies
#define AST   132          // smem row stride (floats)
#define TILES 391          // ceil(NN/128)
#define GEMX  74           // persistent CTAs per matrix (74*2 = 148 = 1 wave)

// ---------------- scratch ----------------------------------------------------
__device__ __half2 g_supp_h[NN * (DD / 2)];    // fp16 support
__device__ float g_tmp[NN * DD];
__device__ float g_statpart[2 * NCOPY * 2 * DD];
__device__ float g_bnab[2 * 2 * DD];           // [layer][a(128) | b(128)]
__device__ float g_s1[NN];
__device__ float g_s2[NN];
__device__ int   g_counts[NN];
__device__ int   g_rowstart[NN + 1];
__device__ int   g_cursor[NN];
__device__ int   g_scan_flag[SCANB];
__device__ int   g_scan_agg[SCANB];
__device__ int   g_scan_pref[SCANB];
__device__ int2  g_csr[EADJ];

// ---------------- helpers ----------------------------------------------------
__device__ __forceinline__ float f2tf32(float f) {
    uint32_t r;
    asm("cvt.rna.tf32.f32 %0, %1;" : "=r"(r) : "f"(f));
    return __uint_as_float(r);
}

__device__ __forceinline__ void mma_tf32(float* c, const uint32_t* a, const uint32_t* b) {
    asm volatile(
        "mma.sync.aligned.m16n8k8.row.col.f32.tf32.tf32.f32 "
        "{%0,%1,%2,%3}, {%4,%5,%6,%7}, {%8,%9}, {%0,%1,%2,%3};\n"
        : "+f"(c[0]), "+f"(c[1]), "+f"(c[2]), "+f"(c[3])
        : "r"(a[0]), "r"(a[1]), "r"(a[2]), "r"(a[3]), "r"(b[0]), "r"(b[1]));
}

// ---------------- persistent tf32 GEMM ---------------------------------------
// grid (GEMX, 2): by picks W (-> support, half) or Wself (-> tmp + bias).
// 256 threads = 8 warps (2 wy x 4 wx), warp tile 64x32 (mt 0..3, nt 0..3).
// Register prefetch of next A tile (16 float4/thread); no spills at 255-reg cap.
// Crossbar model: 393KB LDS/tile = 3072cyc < 4096cyc tensor -> tensor-bound.
__global__ __launch_bounds__(256) void gemm_persist(
    const float* __restrict__ A,
    const float* __restrict__ W,
    const float* __restrict__ Wself,
    const float* __restrict__ bias,
    const float* __restrict__ bn_ab,    // null -> no BN on A
    __half2* __restrict__ suppH,
    float* __restrict__ outtmp)
{
    extern __shared__ float sm[];
    float* Bs  = sm;                    // 128 x AST
    float* As0 = sm + DD * AST;         // 128 x AST
    float* As1 = As0 + DD * AST;        // 128 x AST

    const int   by  = blockIdx.y;
    const float* B  = by ? Wself : W;
    const int tid  = threadIdx.x;
    const int wid  = tid >> 5;
    const int lane = tid & 31;
    const int wy   = wid >> 2;          // 0..1: 64-row slice
    const int wx   = wid & 3;           // 0..3: 32-col slice
    const int g    = lane >> 2;
    const int tig  = lane & 3;

    // ---- stage B once: Bs[n][k] transposed + converted ----
#pragma unroll
    for (int i = 0; i < 4; i++) {
        int k  = lane;                          // 0..31
        int n0 = (wid + i * 8) << 2;            // 0..124
#pragma unroll
        for (int kc = 0; kc < DD; kc += 32) {
            float4 v = *(const float4*)(B + (size_t)(kc + k) * DD + n0);
            Bs[(n0 + 0) * AST + kc + k] = f2tf32(v.x);
            Bs[(n0 + 1) * AST + kc + k] = f2tf32(v.y);
            Bs[(n0 + 2) * AST + kc + k] = f2tf32(v.z);
            Bs[(n0 + 3) * AST + kc + k] = f2tf32(v.w);
        }
    }

    // bias fragment (by=1 only)
    float2 bb[4];
#pragma unroll
    for (int nt = 0; nt < 4; nt++) {
        int col = wx * 32 + nt * 8 + (tig << 1);
        bb[nt] = by ? *(const float2*)(bias + col) : make_float2(0.f, 0.f);
    }

    float4 pf[16];
    const int t0 = blockIdx.x;

    // prefetch + stage tile 0
#pragma unroll
    for (int p = 0; p < 16; p++) {
        int idx = tid + p * 256;
        int row = idx >> 5, c4 = idx & 31;
        int gr  = t0 * 128 + row;
        pf[p] = (gr < NN) ? *(const float4*)(A + (size_t)gr * DD + (c4 << 2))
                          : make_float4(0.f, 0.f, 0.f, 0.f);
    }
#pragma unroll
    for (int p = 0; p < 16; p++) {
        int idx = tid + p * 256;
        int row = idx >> 5, c4 = idx & 31;
        int kv  = c4 << 2;
        float4 v = pf[p];
        if (bn_ab) {
            float4 a4 = *(const float4*)(bn_ab + kv);
            float4 b4 = *(const float4*)(bn_ab + DD + kv);
            v.x = fmaxf(0.f, fmaf(v.x, a4.x, b4.x));
            v.y = fmaxf(0.f, fmaf(v.y, a4.y, b4.y));
            v.z = fmaxf(0.f, fmaf(v.z, a4.z, b4.z));
            v.w = fmaxf(0.f, fmaf(v.w, a4.w, b4.w));
        }
        float4 t4;
        t4.x = f2tf32(v.x); t4.y = f2tf32(v.y);
        t4.z = f2tf32(v.z); t4.w = f2tf32(v.w);
        *(float4*)(&As0[row * AST + kv]) = t4;
    }
    __syncthreads();

    float* cur = As0;
    float* nxt = As1;

    for (int t = t0; t < TILES; t += GEMX) {
        const int tn = t + GEMX;
        // ---- prefetch next tile's A into registers (overlaps compute) ----
        if (tn < TILES) {
#pragma unroll
            for (int p = 0; p < 16; p++) {
                int idx = tid + p * 256;
                int row = idx >> 5, c4 = idx & 31;
                int gr  = tn * 128 + row;
                pf[p] = (gr < NN) ? *(const float4*)(A + (size_t)gr * DD + (c4 << 2))
                                  : make_float4(0.f, 0.f, 0.f, 0.f);
            }
        }

        // ---- compute 128x128 tile (warp tile 64x32) ----
        float acc[4][4][4];
#pragma unroll
        for (int mt = 0; mt < 4; mt++)
#pragma unroll
            for (int nt = 0; nt < 4; nt++)
#pragma unroll
                for (int i = 0; i < 4; i++) acc[mt][nt][i] = 0.0f;

#pragma unroll
        for (int ks = 0; ks < 16; ks++) {
            int kk = ks * 8 + tig;
            uint32_t af[4][4];
#pragma unroll
            for (int mt = 0; mt < 4; mt++) {
                int rb = wy * 64 + mt * 16;
                af[mt][0] = __float_as_uint(cur[(rb + g) * AST + kk]);
                af[mt][1] = __float_as_uint(cur[(rb + g + 8) * AST + kk]);
                af[mt][2] = __float_as_uint(cur[(rb + g) * AST + kk + 4]);
                af[mt][3] = __float_as_uint(cur[(rb + g + 8) * AST + kk + 4]);
            }
            uint32_t bf[4][2];
#pragma unroll
            for (int nt = 0; nt < 4; nt++) {
                int n = wx * 32 + nt * 8 + g;
                bf[nt][0] = __float_as_uint(Bs[n * AST + kk]);
                bf[nt][1] = __float_as_uint(Bs[n * AST + kk + 4]);
            }
#pragma unroll
            for (int mt = 0; mt < 4; mt++)
#pragma unroll
                for (int nt = 0; nt < 4; nt++)
                    mma_tf32(acc[mt][nt], af[mt], bf[nt]);
        }

        // ---- epilogue for tile t ----
        const int m0 = t * 128;
#pragma unroll
        for (int nt = 0; nt < 4; nt++) {
            int col = wx * 32 + nt * 8 + (tig << 1);
#pragma unroll
            for (int mt = 0; mt < 4; mt++) {
                int r0 = m0 + wy * 64 + mt * 16 + g;
                int r1 = r0 + 8;
                float2 v0 = make_float2(acc[mt][nt][0] + bb[nt].x, acc[mt][nt][1] + bb[nt].y);
                float2 v1 = make_float2(acc[mt][nt][2] + bb[nt].x, acc[mt][nt][3] + bb[nt].y);
                if (by) {
                    if (r0 < NN) *(float2*)(outtmp + (size_t)r0 * DD + col) = v0;
                    if (r1 < NN) *(float2*)(outtmp + (size_t)r1 * DD + col) = v1;
                } else {
                    if (r0 < NN) suppH[(size_t)r0 * (DD / 2) + (col >> 1)] = __float22half2_rn(v0);
                    if (r1 < NN) suppH[(size_t)r1 * (DD / 2) + (col >> 1)] = __float22half2_rn(v1);
                }
            }
        }

        // ---- convert + store next tile into the spare buffer ----
        if (tn < TILES) {
#pragma unroll
            for (int p = 0; p < 16; p++) {
                int idx = tid + p * 256;
                int row = idx >> 5, c4 = idx & 31;
                int kv  = c4 << 2;
                float4 v = pf[p];
                if (bn_ab) {
                    float4 a4 = *(const float4*)(bn_ab + kv);
                    float4 b4 = *(const float4*)(bn_ab + DD + kv);
                    v.x = fmaxf(0.f, fmaf(v.x, a4.x, b4.x));
                    v.y = fmaxf(0.f, fmaf(v.y, a4.y, b4.y));
                    v.z = fmaxf(0.f, fmaf(v.z, a4.z, b4.z));
                    v.w = fmaxf(0.f, fmaf(v.w, a4.w, b4.w));
                }
                float4 t4;
                t4.x = f2tf32(v.x); t4.y = f2tf32(v.y);
                t4.z = f2tf32(v.z); t4.w = f2tf32(v.w);
                *(float4*)(&nxt[row * AST + kv]) = t4;
            }
        }
        __syncthreads();
        float* tmpp = cur; cur = nxt; nxt = tmpp;
    }
}

// ---------------- CSR build ---------------------------------------------------
__global__ __launch_bounds__(256) void histo(const int* __restrict__ rows)
{
    int e = blockIdx.x * blockDim.x + threadIdx.x;
    if (e < EADJ) atomicAdd(&g_counts[rows[e]], 1);
}

__global__ __launch_bounds__(256) void scan_lookback()
{
    __shared__ int ws[8];
    __shared__ int s_prefix;
    const int bid = blockIdx.x;
    const int tid = threadIdx.x, lane = tid & 31, w = tid >> 5;
    int i = bid * 256 + tid;
    int v = (i < NN) ? g_counts[i] : 0;
    int inc = v;
#pragma unroll
    for (int o = 1; o < 32; o <<= 1) {
        int n = __shfl_up_sync(0xFFFFFFFFu, inc, o);
        if (lane >= o) inc += n;
    }
    if (lane == 31) ws[w] = inc;
    __syncthreads();
    if (w == 0 && lane < 8) {
        int s = ws[lane];
#pragma unroll
        for (int o = 1; o < 8; o <<= 1) {
            int n = __shfl_up_sync(0xFFu, s, o);
            if (lane >= o) s += n;
        }
        ws[lane] = s;
    }
    __syncthreads();
    int local_excl = (w ? ws[w - 1] : 0) + inc - v;
    int total = ws[7];

    if (tid == 0) {
        if (bid == 0) {
            g_scan_pref[0] = total;
            __threadfence();
            g_scan_flag[0] = 2;
            s_prefix = 0;
        } else {
            g_scan_agg[bid] = total;
            __threadfence();
            g_scan_flag[bid] = 1;
            int pref = 0;
            for (int j = bid - 1; j >= 0; j--) {
                int f;
                do { f = *(volatile int*)&g_scan_flag[j]; } while (f == 0);
                __threadfence();
                if (f == 2) { pref += *(volatile int*)&g_scan_pref[j]; break; }
                pref += *(volatile int*)&g_scan_agg[j];
            }
            g_scan_pref[bid] = pref + total;
            __threadfence();
            g_scan_flag[bid] = 2;
            s_prefix = pref;
        }
    }
    __syncthreads();
    int excl = s_prefix + local_excl;
    if (i < NN) { g_rowstart[i] = excl; g_cursor[i] = excl; }
    if (i == 0) g_rowstart[NN] = EADJ;
}

__global__ __launch_bounds__(256) void scatter_csr(
    const int* __restrict__ rows, const int* __restrict__ cols,
    const float* __restrict__ vals)
{
    int e = blockIdx.x * blockDim.x + threadIdx.x;
    if (e >= EADJ) return;
    int p = atomicAdd(&g_cursor[rows[e]], 1);
    g_csr[p] = make_int2(cols[e], __float_as_int(vals[e]));
}

// ---------------- CSR SpMM (half gather, 1 row/warp) + fused BN stats --------
__global__ __launch_bounds__(256) void spmm_csr(
    const __half2* __restrict__ S2, float* __restrict__ Out,
    float* __restrict__ statpart)
{
    int lane = threadIdx.x & 31;
    int w    = threadIdx.x >> 5;
    int cg   = lane << 2;
    const int h2off = lane << 1;
    int row  = blockIdx.x * 8 + w;

    float4 s = make_float4(0.f, 0.f, 0.f, 0.f);
    float4 q = make_float4(0.f, 0.f, 0.f, 0.f);

    if (row < NN) {
        int e0 = g_rowstart[row];
        int e1 = g_rowstart[row + 1];
        float4 acc = make_float4(0.f, 0.f, 0.f, 0.f);
        int i = e0;
        for (; i + 4 <= e1; i += 4) {
            int2 cv0 = g_csr[i + 0];
            int2 cv1 = g_csr[i + 1];
            int2 cv2 = g_csr[i + 2];
            int2 cv3 = g_csr[i + 3];
            uint2 r0 = *(const uint2*)(S2 + (size_t)cv0.x * (DD / 2) + h2off);
            uint2 r1 = *(const uint2*)(S2 + (size_t)cv1.x * (DD / 2) + h2off);
            uint2 r2 = *(const uint2*)(S2 + (size_t)cv2.x * (DD / 2) + h2off);
            uint2 r3 = *(const uint2*)(S2 + (size_t)cv3.x * (DD / 2) + h2off);
            float v0 = __int_as_float(cv0.y), v1 = __int_as_float(cv1.y);
            float v2 = __int_as_float(cv2.y), v3 = __int_as_float(cv3.y);
            float2 a0 = __half22float2(*(__half2*)&r0.x), b0 = __half22float2(*(__half2*)&r0.y);
            float2 a1 = __half22float2(*(__half2*)&r1.x), b1 = __half22float2(*(__half2*)&r1.y);
            float2 a2 = __half22float2(*(__half2*)&r2.x), b2 = __half22float2(*(__half2*)&r2.y);
            float2 a3 = __half22float2(*(__half2*)&r3.x), b3 = __half22float2(*(__half2*)&r3.y);
            acc.x += v0 * a0.x + v1 * a1.x + v2 * a2.x + v3 * a3.x;
            acc.y += v0 * a0.y + v1 * a1.y + v2 * a2.y + v3 * a3.y;
            acc.z += v0 * b0.x + v1 * b1.x + v2 * b2.x + v3 * b3.x;
            acc.w += v0 * b0.y + v1 * b1.y + v2 * b2.y + v3 * b3.y;
        }
        for (; i < e1; i++) {
            int2 cv = g_csr[i];
            float vv = __int_as_float(cv.y);
            uint2 rr = *(const uint2*)(S2 + (size_t)cv.x * (DD / 2) + h2off);
            float2 aa = __half22float2(*(__half2*)&rr.x);
            float2 bbv = __half22float2(*(__half2*)&rr.y);
            acc.x += vv * aa.x; acc.y += vv * aa.y;
            acc.z += vv * bbv.x; acc.w += vv * bbv.y;
        }
        float4* p = (float4*)(Out + (size_t)row * DD + cg);
        float4 t = *p;
        t.x += acc.x; t.y += acc.y; t.z += acc.z; t.w += acc.w;
        *p = t;
        s = t;
        q.x = t.x * t.x; q.y = t.y * t.y;
        q.z = t.z * t.z; q.w = t.w * t.w;
    }

    __shared__ float4 ss[8][32];
    __shared__ float4 qq[8][32];
    ss[w][lane] = s;
    qq[w][lane] = q;
    __syncthreads();
    if (w == 0) {
#pragma unroll
        for (int k = 1; k < 8; k++) {
            float4 a = ss[k][lane], b = qq[k][lane];
            s.x += a.x; s.y += a.y; s.z += a.z; s.w += a.w;
            q.x += b.x; q.y += b.y; q.z += b.z; q.w += b.w;
        }
        float* base = statpart + (size_t)(blockIdx.x & (NCOPY - 1)) * 2 * DD;
        atomicAdd((float4*)(base + cg), s);
        atomicAdd((float4*)(base + DD + cg), q);
    }
}

// fold NCOPY partials -> BN scale/shift
__global__ __launch_bounds__(128) void reduce_stats(
    const float* __restrict__ statpart,
    const float* __restrict__ gm, const float* __restrict__ be,
    float* __restrict__ ab)
{
    int col = threadIdx.x;
    float s = 0.f, q = 0.f;
#pragma unroll
    for (int c = 0; c < NCOPY; c++) {
        s += statpart[c * 2 * DD + col];
        q += statpart[c * 2 * DD + DD + col];
    }
    const float invN = 1.0f / (float)NN;
    float m   = s * invN;
    float var = q * invN - m * m;
    float a   = gm[col] * rsqrtf(var + BNEPS);
    ab[col]      = a;
    ab[DD + col] = be[col] - m * a;
}

// ---------------- node scores (BN layer2 fused) -------------------------------
__global__ __launch_bounds__(256) void node_scores(
    const float* __restrict__ T2,
    const float* __restrict__ ab,
    const float* __restrict__ X,
    const float* __restrict__ Wc)
{
    int warp = (blockIdx.x * blockDim.x + threadIdx.x) >> 5;
    int lane = threadIdx.x & 31;
    if (warp >= NN) return;
    int cg = lane << 2;
    size_t off = (size_t)warp * DD + cg;
    float4 t = *(const float4*)(T2 + off);
    float4 x = *(const float4*)(X + off);
    float4 a4 = *(const float4*)(ab + cg);
    float4 b4 = *(const float4*)(ab + DD + cg);
    float h0 = fmaxf(0.f, fmaf(t.x, a4.x, b4.x)) + x.x;
    float h1 = fmaxf(0.f, fmaf(t.y, a4.y, b4.y)) + x.y;
    float h2 = fmaxf(0.f, fmaf(t.z, a4.z, b4.z)) + x.z;
    float h3 = fmaxf(0.f, fmaf(t.w, a4.w, b4.w)) + x.w;
    float4 w1 = *(const float4*)(Wc + cg);
    float4 w2 = *(const float4*)(Wc + DD + cg);
    float s1 = h0 * w1.x + h1 * w1.y + h2 * w1.z + h3 * w1.w;
    float s2 = h0 * w2.x + h1 * w2.y + h2 * w2.z + h3 * w2.w;
#pragma unroll
    for (int o = 16; o; o >>= 1) {
        s1 += __shfl_xor_sync(0xFFFFFFFFu, s1, o);
        s2 += __shfl_xor_sync(0xFFFFFFFFu, s2, o);
    }
    if (lane == 0) {
        g_s1[warp] = s1;
        g_s2[warp] = s2;
    }
}

// ---------------- edge prediction ---------------------------------------------
__global__ __launch_bounds__(256) void edge_pred(
    const int* __restrict__ ei,
    const float* __restrict__ bc,
    float* __restrict__ out)
{
    int e = blockIdx.x * blockDim.x + threadIdx.x;
    if (e >= EPRED) return;
    float z = g_s1[ei[e]] + g_s2[ei[e + EPRED]] + bc[0];
    out[e] = 1.0f / (1.0f + expf(-z));
}

// ---------------- launch ------------------------------------------------------
extern "C" void kernel_launch(void* const* d_in, const int* in_sizes, int n_in,
                              void* d_out, int out_size)
{
    const float* x       = (const float*)d_in[0];
    const int*   adj_row = (const int*)d_in[1];
    const int*   adj_col = (const int*)d_in[2];
    const float* adj_val = (const float*)d_in[3];
    const int*   eidx    = (const int*)d_in[4];
    const float* W       = (const float*)d_in[5];
    const float* Wself   = (const float*)d_in[6];
    const float* b       = (const float*)d_in[7];
    const float* gamma   = (const float*)d_in[8];
    const float* beta    = (const float*)d_in[9];
    const float* Wc      = (const float*)d_in[10];
    const float* bc      = (const float*)d_in[11];
    float* out           = (float*)d_out;

    __half2* suppH; float *tmp, *statpart, *bnab;
    int *counts, *flags;
    cudaGetSymbolAddress((void**)&suppH,    g_supp_h);
    cudaGetSymbolAddress((void**)&tmp,      g_tmp);
    cudaGetSymbolAddress((void**)&statpart, g_statpart);
    cudaGetSymbolAddress((void**)&bnab,     g_bnab);
    cudaGetSymbolAddress((void**)&counts,   g_counts);
    cudaGetSymbolAddress((void**)&flags,    g_scan_flag);

    const int gemm_smem = 3 * DD * AST * (int)sizeof(float);   // B + 2 A bufs
    cudaFuncSetAttribute(gemm_persist,
                         cudaFuncAttributeMaxDynamicSharedMemorySize, gemm_smem);

    const dim3 gemm_grid(GEMX, 2);
    const int eb = (EADJ + 255) / 256;
    const int spmm_blocks = (NN + 7) / 8;

    cudaMemsetAsync(counts, 0, NN * sizeof(int));
    cudaMemsetAsync(flags, 0, SCANB * sizeof(int));
    cudaMemsetAsync(statpart, 0, 2 * NCOPY * 2 * DD * sizeof(float));

    // CSR build
    histo<<<eb, 256>>>(adj_row);
    scan_lookback<<<SCANB, 256>>>();
    scatter_csr<<<eb, 256>>>(adj_row, adj_col, adj_val);

    // layer 1
    gemm_persist<<<gemm_grid, 256, gemm_smem>>>(x, W, Wself, b, nullptr,
                                                suppH, tmp);
    spmm_csr<<<spmm_blocks, 256>>>(suppH, tmp, statpart);
    reduce_stats<<<1, 128>>>(statpart, gamma, beta, bnab);

    // layer 2 (BN+ReLU fused into A staging)
    gemm_persist<<<gemm_grid, 256, gemm_smem>>>(tmp, W + DD * DD,
                                                Wself + DD * DD, b + DD,
                                                bnab, suppH, tmp);
    spmm_csr<<<spmm_blocks, 256>>>(suppH, tmp, statpart + NCOPY * 2 * DD);
    reduce_stats<<<1, 128>>>(statpart + NCOPY * 2 * DD, gamma + DD, beta + DD,
                             bnab + 2 * DD);

    node_scores<<<(NN * 32 + 255) / 256, 256>>>(tmp, bnab + 2 * DD, x, Wc);
    edge_pred<<<(EPRED + 255) / 256, 256>>>(eidx, bc, out);
}

// round 10
// speedup vs baseline: 1.2172x; 1.0207x over previous
#include <cuda_runtime.h>
#include <cuda_fp16.h>
#include <math.h>
#include <stdint.h>

#define NN    50000
#define DD    128
#define EADJ  800000
#define EPRED 500000
#define BNEPS 1e-5f
#define SCANB 196          // ceil(NN/256)
#define NCOPY 32           // stat partial copies
#define AST   132          // smem row stride (floats)
#define TILES 391          // ceil(NN/128)
#define GEMC  148          // persistent CTAs (1 wave)

// ---------------- scratch ----------------------------------------------------
__device__ __half2 g_supp_h[NN * (DD / 2)];    // fp16 support
__device__ float g_tmp[NN * DD];
__device__ float g_statpart[2 * NCOPY * 2 * DD];
__device__ float g_bnab[2 * 2 * DD];           // [layer][a(128) | b(128)]
__device__ float g_s1[NN];
__device__ float g_s2[NN];
__device__ int   g_counts[NN];
__device__ int   g_rowstart[NN + 1];
__device__ int   g_cursor[NN];
__device__ int   g_scan_flag[SCANB];
__device__ int   g_scan_agg[SCANB];
__device__ int   g_scan_pref[SCANB];
__device__ int2  g_csr[EADJ];

// ---------------- helpers ----------------------------------------------------
__device__ __forceinline__ float f2tf32(float f) {
    uint32_t r;
    asm("cvt.rna.tf32.f32 %0, %1;" : "=r"(r) : "f"(f));
    return __uint_as_float(r);
}

__device__ __forceinline__ void mma_tf32(float* c, const uint32_t* a, const uint32_t* b) {
    asm volatile(
        "mma.sync.aligned.m16n8k8.row.col.f32.tf32.tf32.f32 "
        "{%0,%1,%2,%3}, {%4,%5,%6,%7}, {%8,%9}, {%0,%1,%2,%3};\n"
        : "+f"(c[0]), "+f"(c[1]), "+f"(c[2]), "+f"(c[3])
        : "r"(a[0]), "r"(a[1]), "r"(a[2]), "r"(a[3]), "r"(b[0]), "r"(b[1]));
}

// ---------------- merged persistent tf32 dual GEMM ---------------------------
// ONE launch computes BOTH support = A@W (half) and tmp = A@Wself + bias (f32).
// 148 CTAs, 256 threads = 8 warps (wy 2 x wx 4), warp tile 64 rows x 32 cols
// per matrix (two independent acc sets -> 32 HMMA chains per warp per ks).
// Both B matrices resident in smem; A tile staged once per tile (halved work).
__global__ __launch_bounds__(256) void gemm_merged(
    const float* __restrict__ A,
    const float* __restrict__ W,
    const float* __restrict__ Wself,
    const float* __restrict__ bias,
    const float* __restrict__ bn_ab,    // null -> no BN on A
    __half2* __restrict__ suppH,
    float* __restrict__ outtmp)
{
    extern __shared__ float sm[];
    float* BsW = sm;                    // 128 x AST
    float* BsS = sm + DD * AST;         // 128 x AST
    float* As  = sm + 2 * DD * AST;     // 128 x AST

    const int tid  = threadIdx.x;
    const int wid  = tid >> 5;
    const int lane = tid & 31;
    const int wy   = wid >> 2;          // 0..1: 64-row slice
    const int wx   = wid & 3;           // 0..3: 32-col slice
    const int g    = lane >> 2;
    const int tig  = lane & 3;

    // ---- stage both B matrices once: Bs[n][k] transposed + converted ----
#pragma unroll
    for (int i = 0; i < 4; i++) {
        int k  = lane;                          // 0..31
        int n0 = (wid + i * 8) << 2;            // 0..124
#pragma unroll
        for (int kc = 0; kc < DD; kc += 32) {
            float4 vw = *(const float4*)(W + (size_t)(kc + k) * DD + n0);
            BsW[(n0 + 0) * AST + kc + k] = f2tf32(vw.x);
            BsW[(n0 + 1) * AST + kc + k] = f2tf32(vw.y);
            BsW[(n0 + 2) * AST + kc + k] = f2tf32(vw.z);
            BsW[(n0 + 3) * AST + kc + k] = f2tf32(vw.w);
            float4 vs = *(const float4*)(Wself + (size_t)(kc + k) * DD + n0);
            BsS[(n0 + 0) * AST + kc + k] = f2tf32(vs.x);
            BsS[(n0 + 1) * AST + kc + k] = f2tf32(vs.y);
            BsS[(n0 + 2) * AST + kc + k] = f2tf32(vs.z);
            BsS[(n0 + 3) * AST + kc + k] = f2tf32(vs.w);
        }
    }

    // bias fragment for the Wself output
    float2 bb[4];
#pragma unroll
    for (int nt = 0; nt < 4; nt++) {
        int col = wx * 32 + nt * 8 + (tig << 1);
        bb[nt] = *(const float2*)(bias + col);
    }
    __syncthreads();

    for (int t = blockIdx.x; t < TILES; t += GEMC) {
        const int m0 = t * 128;
        // ---- stage A tile: 16 float4/thread, BN+ReLU fused, cvt RN ----
#pragma unroll
        for (int p = 0; p < 16; p++) {
            int idx = tid + p * 256;
            int row = idx >> 5, c4 = idx & 31;
            int kv  = c4 << 2;
            int gr  = m0 + row;
            float4 v = make_float4(0.f, 0.f, 0.f, 0.f);
            if (gr < NN) v = *(const float4*)(A + (size_t)gr * DD + kv);
            if (bn_ab) {
                float4 a4 = *(const float4*)(bn_ab + kv);
                float4 b4 = *(const float4*)(bn_ab + DD + kv);
                v.x = fmaxf(0.f, fmaf(v.x, a4.x, b4.x));
                v.y = fmaxf(0.f, fmaf(v.y, a4.y, b4.y));
                v.z = fmaxf(0.f, fmaf(v.z, a4.z, b4.z));
                v.w = fmaxf(0.f, fmaf(v.w, a4.w, b4.w));
            }
            float4 t4;
            t4.x = f2tf32(v.x); t4.y = f2tf32(v.y);
            t4.z = f2tf32(v.z); t4.w = f2tf32(v.w);
            *(float4*)(&As[row * AST + kv]) = t4;
        }
        __syncthreads();

        // ---- compute: two acc sets share the A fragments ----
        float accW[4][4][4];
        float accS[4][4][4];
#pragma unroll
        for (int mt = 0; mt < 4; mt++)
#pragma unroll
            for (int nt = 0; nt < 4; nt++)
#pragma unroll
                for (int i = 0; i < 4; i++) { accW[mt][nt][i] = 0.f; accS[mt][nt][i] = 0.f; }

#pragma unroll
        for (int ks = 0; ks < 16; ks++) {
            int kk = ks * 8 + tig;
            uint32_t af[4][4];
#pragma unroll
            for (int mt = 0; mt < 4; mt++) {
                int rb = wy * 64 + mt * 16;
                af[mt][0] = __float_as_uint(As[(rb + g) * AST + kk]);
                af[mt][1] = __float_as_uint(As[(rb + g + 8) * AST + kk]);
                af[mt][2] = __float_as_uint(As[(rb + g) * AST + kk + 4]);
                af[mt][3] = __float_as_uint(As[(rb + g + 8) * AST + kk + 4]);
            }
            uint32_t bfW[4][2], bfS[4][2];
#pragma unroll
            for (int nt = 0; nt < 4; nt++) {
                int n = wx * 32 + nt * 8 + g;
                bfW[nt][0] = __float_as_uint(BsW[n * AST + kk]);
                bfW[nt][1] = __float_as_uint(BsW[n * AST + kk + 4]);
                bfS[nt][0] = __float_as_uint(BsS[n * AST + kk]);
                bfS[nt][1] = __float_as_uint(BsS[n * AST + kk + 4]);
            }
#pragma unroll
            for (int mt = 0; mt < 4; mt++)
#pragma unroll
                for (int nt = 0; nt < 4; nt++) {
                    mma_tf32(accW[mt][nt], af[mt], bfW[nt]);
                    mma_tf32(accS[mt][nt], af[mt], bfS[nt]);
                }
        }

        // ---- epilogue: both outputs ----
#pragma unroll
        for (int nt = 0; nt < 4; nt++) {
            int col = wx * 32 + nt * 8 + (tig << 1);
#pragma unroll
            for (int mt = 0; mt < 4; mt++) {
                int r0 = m0 + wy * 64 + mt * 16 + g;
                int r1 = r0 + 8;
                if (r0 < NN) {
                    float2 w0 = make_float2(accW[mt][nt][0], accW[mt][nt][1]);
                    suppH[(size_t)r0 * (DD / 2) + (col >> 1)] = __float22half2_rn(w0);
                    float2 s0 = make_float2(accS[mt][nt][0] + bb[nt].x, accS[mt][nt][1] + bb[nt].y);
                    *(float2*)(outtmp + (size_t)r0 * DD + col) = s0;
                }
                if (r1 < NN) {
                    float2 w1 = make_float2(accW[mt][nt][2], accW[mt][nt][3]);
                    suppH[(size_t)r1 * (DD / 2) + (col >> 1)] = __float22half2_rn(w1);
                    float2 s1 = make_float2(accS[mt][nt][2] + bb[nt].x, accS[mt][nt][3] + bb[nt].y);
                    *(float2*)(outtmp + (size_t)r1 * DD + col) = s1;
                }
            }
        }
        __syncthreads();
    }
}

// ---------------- CSR build ---------------------------------------------------
__global__ __launch_bounds__(256) void histo(const int* __restrict__ rows)
{
    int e = blockIdx.x * blockDim.x + threadIdx.x;
    if (e < EADJ) atomicAdd(&g_counts[rows[e]], 1);
}

__global__ __launch_bounds__(256) void scan_lookback()
{
    __shared__ int ws[8];
    __shared__ int s_prefix;
    const int bid = blockIdx.x;
    const int tid = threadIdx.x, lane = tid & 31, w = tid >> 5;
    int i = bid * 256 + tid;
    int v = (i < NN) ? g_counts[i] : 0;
    int inc = v;
#pragma unroll
    for (int o = 1; o < 32; o <<= 1) {
        int n = __shfl_up_sync(0xFFFFFFFFu, inc, o);
        if (lane >= o) inc += n;
    }
    if (lane == 31) ws[w] = inc;
    __syncthreads();
    if (w == 0 && lane < 8) {
        int s = ws[lane];
#pragma unroll
        for (int o = 1; o < 8; o <<= 1) {
            int n = __shfl_up_sync(0xFFu, s, o);
            if (lane >= o) s += n;
        }
        ws[lane] = s;
    }
    __syncthreads();
    int local_excl = (w ? ws[w - 1] : 0) + inc - v;
    int total = ws[7];

    if (tid == 0) {
        if (bid == 0) {
            g_scan_pref[0] = total;
            __threadfence();
            g_scan_flag[0] = 2;
            s_prefix = 0;
        } else {
            g_scan_agg[bid] = total;
            __threadfence();
            g_scan_flag[bid] = 1;
            int pref = 0;
            for (int j = bid - 1; j >= 0; j--) {
                int f;
                do { f = *(volatile int*)&g_scan_flag[j]; } while (f == 0);
                __threadfence();
                if (f == 2) { pref += *(volatile int*)&g_scan_pref[j]; break; }
                pref += *(volatile int*)&g_scan_agg[j];
            }
            g_scan_pref[bid] = pref + total;
            __threadfence();
            g_scan_flag[bid] = 2;
            s_prefix = pref;
        }
    }
    __syncthreads();
    int excl = s_prefix + local_excl;
    if (i < NN) { g_rowstart[i] = excl; g_cursor[i] = excl; }
    if (i == 0) g_rowstart[NN] = EADJ;
}

__global__ __launch_bounds__(256) void scatter_csr(
    const int* __restrict__ rows, const int* __restrict__ cols,
    const float* __restrict__ vals)
{
    int e = blockIdx.x * blockDim.x + threadIdx.x;
    if (e >= EADJ) return;
    int p = atomicAdd(&g_cursor[rows[e]], 1);
    g_csr[p] = make_int2(cols[e], __float_as_int(vals[e]));
}

// ---------------- CSR SpMM (half gather, 1 row/warp) + fused BN stats --------
__global__ __launch_bounds__(256) void spmm_csr(
    const __half2* __restrict__ S2, float* __restrict__ Out,
    float* __restrict__ statpart)
{
    int lane = threadIdx.x & 31;
    int w    = threadIdx.x >> 5;
    int cg   = lane << 2;
    const int h2off = lane << 1;
    int row  = blockIdx.x * 8 + w;

    float4 s = make_float4(0.f, 0.f, 0.f, 0.f);
    float4 q = make_float4(0.f, 0.f, 0.f, 0.f);

    if (row < NN) {
        int e0 = g_rowstart[row];
        int e1 = g_rowstart[row + 1];
        float4 acc = make_float4(0.f, 0.f, 0.f, 0.f);
        int i = e0;
        for (; i + 4 <= e1; i += 4) {
            int2 cv0 = g_csr[i + 0];
            int2 cv1 = g_csr[i + 1];
            int2 cv2 = g_csr[i + 2];
            int2 cv3 = g_csr[i + 3];
            uint2 r0 = *(const uint2*)(S2 + (size_t)cv0.x * (DD / 2) + h2off);
            uint2 r1 = *(const uint2*)(S2 + (size_t)cv1.x * (DD / 2) + h2off);
            uint2 r2 = *(const uint2*)(S2 + (size_t)cv2.x * (DD / 2) + h2off);
            uint2 r3 = *(const uint2*)(S2 + (size_t)cv3.x * (DD / 2) + h2off);
            float v0 = __int_as_float(cv0.y), v1 = __int_as_float(cv1.y);
            float v2 = __int_as_float(cv2.y), v3 = __int_as_float(cv3.y);
            float2 a0 = __half22float2(*(__half2*)&r0.x), b0 = __half22float2(*(__half2*)&r0.y);
            float2 a1 = __half22float2(*(__half2*)&r1.x), b1 = __half22float2(*(__half2*)&r1.y);
            float2 a2 = __half22float2(*(__half2*)&r2.x), b2 = __half22float2(*(__half2*)&r2.y);
            float2 a3 = __half22float2(*(__half2*)&r3.x), b3 = __half22float2(*(__half2*)&r3.y);
            acc.x += v0 * a0.x + v1 * a1.x + v2 * a2.x + v3 * a3.x;
            acc.y += v0 * a0.y + v1 * a1.y + v2 * a2.y + v3 * a3.y;
            acc.z += v0 * b0.x + v1 * b1.x + v2 * b2.x + v3 * b3.x;
            acc.w += v0 * b0.y + v1 * b1.y + v2 * b2.y + v3 * b3.y;
        }
        for (; i < e1; i++) {
            int2 cv = g_csr[i];
            float vv = __int_as_float(cv.y);
            uint2 rr = *(const uint2*)(S2 + (size_t)cv.x * (DD / 2) + h2off);
            float2 aa = __half22float2(*(__half2*)&rr.x);
            float2 bbv = __half22float2(*(__half2*)&rr.y);
            acc.x += vv * aa.x; acc.y += vv * aa.y;
            acc.z += vv * bbv.x; acc.w += vv * bbv.y;
        }
        float4* p = (float4*)(Out + (size_t)row * DD + cg);
        float4 t = *p;
        t.x += acc.x; t.y += acc.y; t.z += acc.z; t.w += acc.w;
        *p = t;
        s = t;
        q.x = t.x * t.x; q.y = t.y * t.y;
        q.z = t.z * t.z; q.w = t.w * t.w;
    }

    __shared__ float4 ss[8][32];
    __shared__ float4 qq[8][32];
    ss[w][lane] = s;
    qq[w][lane] = q;
    __syncthreads();
    if (w == 0) {
#pragma unroll
        for (int k = 1; k < 8; k++) {
            float4 a = ss[k][lane], b = qq[k][lane];
            s.x += a.x; s.y += a.y; s.z += a.z; s.w += a.w;
            q.x += b.x; q.y += b.y; q.z += b.z; q.w += b.w;
        }
        float* base = statpart + (size_t)(blockIdx.x & (NCOPY - 1)) * 2 * DD;
        atomicAdd((float4*)(base + cg), s);
        atomicAdd((float4*)(base + DD + cg), q);
    }
}

// fold NCOPY partials -> BN scale/shift
__global__ __launch_bounds__(128) void reduce_stats(
    const float* __restrict__ statpart,
    const float* __restrict__ gm, const float* __restrict__ be,
    float* __restrict__ ab)
{
    int col = threadIdx.x;
    float s = 0.f, q = 0.f;
#pragma unroll
    for (int c = 0; c < NCOPY; c++) {
        s += statpart[c * 2 * DD + col];
        q += statpart[c * 2 * DD + DD + col];
    }
    const float invN = 1.0f / (float)NN;
    float m   = s * invN;
    float var = q * invN - m * m;
    float a   = gm[col] * rsqrtf(var + BNEPS);
    ab[col]      = a;
    ab[DD + col] = be[col] - m * a;
}

// ---------------- node scores (BN layer2 fused) -------------------------------
__global__ __launch_bounds__(256) void node_scores(
    const float* __restrict__ T2,
    const float* __restrict__ ab,
    const float* __restrict__ X,
    const float* __restrict__ Wc)
{
    int warp = (blockIdx.x * blockDim.x + threadIdx.x) >> 5;
    int lane = threadIdx.x & 31;
    if (warp >= NN) return;
    int cg = lane << 2;
    size_t off = (size_t)warp * DD + cg;
    float4 t = *(const float4*)(T2 + off);
    float4 x = *(const float4*)(X + off);
    float4 a4 = *(const float4*)(ab + cg);
    float4 b4 = *(const float4*)(ab + DD + cg);
    float h0 = fmaxf(0.f, fmaf(t.x, a4.x, b4.x)) + x.x;
    float h1 = fmaxf(0.f, fmaf(t.y, a4.y, b4.y)) + x.y;
    float h2 = fmaxf(0.f, fmaf(t.z, a4.z, b4.z)) + x.z;
    float h3 = fmaxf(0.f, fmaf(t.w, a4.w, b4.w)) + x.w;
    float4 w1 = *(const float4*)(Wc + cg);
    float4 w2 = *(const float4*)(Wc + DD + cg);
    float s1 = h0 * w1.x + h1 * w1.y + h2 * w1.z + h3 * w1.w;
    float s2 = h0 * w2.x + h1 * w2.y + h2 * w2.z + h3 * w2.w;
#pragma unroll
    for (int o = 16; o; o >>= 1) {
        s1 += __shfl_xor_sync(0xFFFFFFFFu, s1, o);
        s2 += __shfl_xor_sync(0xFFFFFFFFu, s2, o);
    }
    if (lane == 0) {
        g_s1[warp] = s1;
        g_s2[warp] = s2;
    }
}

// ---------------- edge prediction ---------------------------------------------
__global__ __launch_bounds__(256) void edge_pred(
    const int* __restrict__ ei,
    const float* __restrict__ bc,
    float* __restrict__ out)
{
    int e = blockIdx.x * blockDim.x + threadIdx.x;
    if (e >= EPRED) return;
    float z = g_s1[ei[e]] + g_s2[ei[e + EPRED]] + bc[0];
    out[e] = 1.0f / (1.0f + expf(-z));
}

// ---------------- launch ------------------------------------------------------
extern "C" void kernel_launch(void* const* d_in, const int* in_sizes, int n_in,
                              void* d_out, int out_size)
{
    const float* x       = (const float*)d_in[0];
    const int*   adj_row = (const int*)d_in[1];
    const int*   adj_col = (const int*)d_in[2];
    const float* adj_val = (const float*)d_in[3];
    const int*   eidx    = (const int*)d_in[4];
    const float* W       = (const float*)d_in[5];
    const float* Wself   = (const float*)d_in[6];
    const float* b       = (const float*)d_in[7];
    const float* gamma   = (const float*)d_in[8];
    const float* beta    = (const float*)d_in[9];
    const float* Wc      = (const float*)d_in[10];
    const float* bc      = (const float*)d_in[11];
    float* out           = (float*)d_out;

    __half2* suppH; float *tmp, *statpart, *bnab;
    int *counts, *flags;
    cudaGetSymbolAddress((void**)&suppH,    g_supp_h);
    cudaGetSymbolAddress((void**)&tmp,      g_tmp);
    cudaGetSymbolAddress((void**)&statpart, g_statpart);
    cudaGetSymbolAddress((void**)&bnab,     g_bnab);
    cudaGetSymbolAddress((void**)&counts,   g_counts);
    cudaGetSymbolAddress((void**)&flags,    g_scan_flag);

    const int gemm_smem = 3 * DD * AST * (int)sizeof(float);   // 2 B + 1 A
    cudaFuncSetAttribute(gemm_merged,
                         cudaFuncAttributeMaxDynamicSharedMemorySize, gemm_smem);

    const int eb = (EADJ + 255) / 256;
    const int spmm_blocks = (NN + 7) / 8;

    cudaMemsetAsync(counts, 0, NN * sizeof(int));
    cudaMemsetAsync(flags, 0, SCANB * sizeof(int));
    cudaMemsetAsync(statpart, 0, 2 * NCOPY * 2 * DD * sizeof(float));

    // CSR build
    histo<<<eb, 256>>>(adj_row);
    scan_lookback<<<SCANB, 256>>>();
    scatter_csr<<<eb, 256>>>(adj_row, adj_col, adj_val);

    // layer 1
    gemm_merged<<<GEMC, 256, gemm_smem>>>(x, W, Wself, b, nullptr, suppH, tmp);
    spmm_csr<<<spmm_blocks, 256>>>(suppH, tmp, statpart);
    reduce_stats<<<1, 128>>>(statpart, gamma, beta, bnab);

    // layer 2 (BN+ReLU fused into A staging)
    gemm_merged<<<GEMC, 256, gemm_smem>>>(tmp, W + DD * DD, Wself + DD * DD,
                                          b + DD, bnab, suppH, tmp);
    spmm_csr<<<spmm_blocks, 256>>>(suppH, tmp, statpart + NCOPY * 2 * DD);
    reduce_stats<<<1, 128>>>(statpart + NCOPY * 2 * DD, gamma + DD, beta + DD,
                             bnab + 2 * DD);

    node_scores<<<(NN * 32 + 255) / 256, 256>>>(tmp, bnab + 2 * DD, x, Wc);
    edge_pred<<<(EPRED + 255) / 256, 256>>>(eidx, bc, out);
}

// round 13
// speedup vs baseline: 1.3022x; 1.0698x over previous
#include <cuda_runtime.h>
#include <cuda_fp16.h>
#include <math.h>
#include <stdint.h>

#define NN    50000
#define DD    128
#define EADJ  800000
#define EPRED 500000
#define BNEPS 1e-5f
#define SCANB 196          // ceil(NN/256)
#define NCOPY 32           // stat partial copies
#define SH    136          // smem half-stride per row (u32 stride 68)
#define TILES 391          // ceil(NN/128)
#define GEMX  148          // CTAs per matrix; grid (148,2) = 296 = 2/SM

// ---------------- scratch ----------------------------------------------------
__device__ __half2 g_supp_h[NN * (DD / 2)];    // fp16 support
__device__ float g_tmp[NN * DD];               // layer-1 pre-BN output
__device__ float g_tmp2[NN * DD];              // layer-2 pre-BN output (no aliasing!)
__device__ float g_statpart[2 * NCOPY * 2 * DD];
__device__ float g_bnab[2 * 2 * DD];           // [layer][a(128) | b(128)]
__device__ float g_s1[NN];
__device__ float g_s2[NN];
__device__ int   g_counts[NN];
__device__ int   g_rowstart[NN + 1];
__device__ int   g_cursor[NN];
__device__ int   g_scan_flag[SCANB];
__device__ int   g_scan_agg[SCANB];
__device__ int   g_scan_pref[SCANB];
__device__ int2  g_csr[EADJ];                  // (col, fp32 val bits)

// ---------------- helpers ----------------------------------------------------
__device__ __forceinline__ void mma_f16(float* c, const uint32_t* a, const uint32_t* b) {
    asm volatile(
        "mma.sync.aligned.m16n8k16.row.col.f32.f16.f16.f32 "
        "{%0,%1,%2,%3}, {%4,%5,%6,%7}, {%8,%9}, {%0,%1,%2,%3};\n"
        : "+f"(c[0]), "+f"(c[1]), "+f"(c[2]), "+f"(c[3])
        : "r"(a[0]), "r"(a[1]), "r"(a[2]), "r"(a[3]), "r"(b[0]), "r"(b[1]));
}

// ---------------- fp16 persistent GEMM ---------------------------------------
// grid (GEMX, 2): by=0 -> support(half) = A@W ; by=1 -> outtmp(f32) = A@Wself+b.
// A and outtmp must NOT alias (layer 2 uses tmp -> tmp2).
// 256 threads = 8 warps (wy 2 x wx 4), warp tile 64x32; m16n8k16 fp16 HMMA.
// 2 CTAs/SM (smem 68KB, <=128 regs) -> 16 warps/SM for latency hiding.
__global__ __launch_bounds__(256, 2) void gemm_h(
    const float* __restrict__ A,
    const float* __restrict__ W,
    const float* __restrict__ Wself,
    const float* __restrict__ bias,
    const float* __restrict__ bn_ab,    // null -> no BN on A
    __half2* __restrict__ suppH,
    float* __restrict__ outtmp)
{
    extern __shared__ __half smh[];
    __half* Bh = smh;                   // 128 x SH
    __half* Ah = smh + DD * SH;         // 128 x SH

    const int   by  = blockIdx.y;
    const float* B  = by ? Wself : W;
    const int tid  = threadIdx.x;
    const int wid  = tid >> 5;
    const int lane = tid & 31;
    const int wy   = wid >> 2;          // 0..1: 64-row slice
    const int wx   = wid & 3;           // 0..3: 32-col slice
    const int g    = lane >> 2;
    const int tig  = lane & 3;

    // ---- stage B once: Bh[n][k] transposed + converted ----
#pragma unroll
    for (int i = 0; i < 4; i++) {
        int k  = lane;                          // 0..31
        int n0 = (wid + i * 8) << 2;            // 0..124
#pragma unroll
        for (int kc = 0; kc < DD; kc += 32) {
            float4 v = *(const float4*)(B + (size_t)(kc + k) * DD + n0);
            Bh[(n0 + 0) * SH + kc + k] = __float2half_rn(v.x);
            Bh[(n0 + 1) * SH + kc + k] = __float2half_rn(v.y);
            Bh[(n0 + 2) * SH + kc + k] = __float2half_rn(v.z);
            Bh[(n0 + 3) * SH + kc + k] = __float2half_rn(v.w);
        }
    }

    // bias fragment (by=1 only)
    float2 bb[4];
#pragma unroll
    for (int nt = 0; nt < 4; nt++) {
        int col = wx * 32 + nt * 8 + (tig << 1);
        bb[nt] = by ? *(const float2*)(bias + col) : make_float2(0.f, 0.f);
    }
    __syncthreads();

    const uint32_t* Au = (const uint32_t*)Ah;
    const uint32_t* Bu = (const uint32_t*)Bh;

    for (int t = blockIdx.x; t < TILES; t += GEMX) {
        const int m0 = t * 128;
        // ---- stage A tile: 16 float4/thread, BN+ReLU fused, -> half ----
#pragma unroll
        for (int p = 0; p < 16; p++) {
            int idx = tid + p * 256;
            int row = idx >> 5, c4 = idx & 31;
            int kv  = c4 << 2;
            int gr  = m0 + row;
            float4 v = make_float4(0.f, 0.f, 0.f, 0.f);
            if (gr < NN) v = *(const float4*)(A + (size_t)gr * DD + kv);
            if (bn_ab) {
                float4 a4 = *(const float4*)(bn_ab + kv);
                float4 b4 = *(const float4*)(bn_ab + DD + kv);
                v.x = fmaxf(0.f, fmaf(v.x, a4.x, b4.x));
                v.y = fmaxf(0.f, fmaf(v.y, a4.y, b4.y));
                v.z = fmaxf(0.f, fmaf(v.z, a4.z, b4.z));
                v.w = fmaxf(0.f, fmaf(v.w, a4.w, b4.w));
            }
            __half2 h01 = __floats2half2_rn(v.x, v.y);
            __half2 h23 = __floats2half2_rn(v.z, v.w);
            uint2 pk;
            pk.x = *(uint32_t*)&h01;
            pk.y = *(uint32_t*)&h23;
            *(uint2*)(&Ah[row * SH + kv]) = pk;    // 8B aligned, conflict-free
        }
        __syncthreads();

        // ---- compute 128x128 tile: 8 ks of m16n8k16 ----
        float acc[4][4][4];
#pragma unroll
        for (int mt = 0; mt < 4; mt++)
#pragma unroll
            for (int nt = 0; nt < 4; nt++)
#pragma unroll
                for (int i = 0; i < 4; i++) acc[mt][nt][i] = 0.0f;

#pragma unroll
        for (int ks = 0; ks < 8; ks++) {
            int kb = ks * 8 + tig;               // u32-index k component
            uint32_t af[4][4];
#pragma unroll
            for (int mt = 0; mt < 4; mt++) {
                int rb = wy * 64 + mt * 16;
                af[mt][0] = Au[(rb + g) * 68 + kb];
                af[mt][1] = Au[(rb + g + 8) * 68 + kb];
                af[mt][2] = Au[(rb + g) * 68 + kb + 4];
                af[mt][3] = Au[(rb + g + 8) * 68 + kb + 4];
            }
            uint32_t bf[4][2];
#pragma unroll
            for (int nt = 0; nt < 4; nt++) {
                int n = wx * 32 + nt * 8 + g;
                bf[nt][0] = Bu[n * 68 + kb];
                bf[nt][1] = Bu[n * 68 + kb + 4];
            }
#pragma unroll
            for (int mt = 0; mt < 4; mt++)
#pragma unroll
                for (int nt = 0; nt < 4; nt++)
                    mma_f16(acc[mt][nt], af[mt], bf[nt]);
        }

        // ---- epilogue ----
#pragma unroll
        for (int nt = 0; nt < 4; nt++) {
            int col = wx * 32 + nt * 8 + (tig << 1);
#pragma unroll
            for (int mt = 0; mt < 4; mt++) {
                int r0 = m0 + wy * 64 + mt * 16 + g;
                int r1 = r0 + 8;
                float2 v0 = make_float2(acc[mt][nt][0] + bb[nt].x, acc[mt][nt][1] + bb[nt].y);
                float2 v1 = make_float2(acc[mt][nt][2] + bb[nt].x, acc[mt][nt][3] + bb[nt].y);
                if (by) {
                    if (r0 < NN) *(float2*)(outtmp + (size_t)r0 * DD + col) = v0;
                    if (r1 < NN) *(float2*)(outtmp + (size_t)r1 * DD + col) = v1;
                } else {
                    if (r0 < NN) suppH[(size_t)r0 * (DD / 2) + (col >> 1)] = __float22half2_rn(v0);
                    if (r1 < NN) suppH[(size_t)r1 * (DD / 2) + (col >> 1)] = __float22half2_rn(v1);
                }
            }
        }
        __syncthreads();
    }
}

// ---------------- CSR build ---------------------------------------------------
__global__ __launch_bounds__(256) void histo(const int* __restrict__ rows)
{
    int e = blockIdx.x * blockDim.x + threadIdx.x;
    if (e < EADJ) atomicAdd(&g_counts[rows[e]], 1);
}

__global__ __launch_bounds__(256) void scan_lookback()
{
    __shared__ int ws[8];
    __shared__ int s_prefix;
    const int bid = blockIdx.x;
    const int tid = threadIdx.x, lane = tid & 31, w = tid >> 5;
    int i = bid * 256 + tid;
    int v = (i < NN) ? g_counts[i] : 0;
    int inc = v;
#pragma unroll
    for (int o = 1; o < 32; o <<= 1) {
        int n = __shfl_up_sync(0xFFFFFFFFu, inc, o);
        if (lane >= o) inc += n;
    }
    if (lane == 31) ws[w] = inc;
    __syncthreads();
    if (w == 0 && lane < 8) {
        int s = ws[lane];
#pragma unroll
        for (int o = 1; o < 8; o <<= 1) {
            int n = __shfl_up_sync(0xFFu, s, o);
            if (lane >= o) s += n;
        }
        ws[lane] = s;
    }
    __syncthreads();
    int local_excl = (w ? ws[w - 1] : 0) + inc - v;
    int total = ws[7];

    if (tid == 0) {
        if (bid == 0) {
            g_scan_pref[0] = total;
            __threadfence();
            g_scan_flag[0] = 2;
            s_prefix = 0;
        } else {
            g_scan_agg[bid] = total;
            __threadfence();
            g_scan_flag[bid] = 1;
            int pref = 0;
            for (int j = bid - 1; j >= 0; j--) {
                int f;
                do { f = *(volatile int*)&g_scan_flag[j]; } while (f == 0);
                __threadfence();
                if (f == 2) { pref += *(volatile int*)&g_scan_pref[j]; break; }
                pref += *(volatile int*)&g_scan_agg[j];
            }
            g_scan_pref[bid] = pref + total;
            __threadfence();
            g_scan_flag[bid] = 2;
            s_prefix = pref;
        }
    }
    __syncthreads();
    int excl = s_prefix + local_excl;
    if (i < NN) { g_rowstart[i] = excl; g_cursor[i] = excl; }
    if (i == 0) g_rowstart[NN] = EADJ;
}

__global__ __launch_bounds__(256) void scatter_csr(
    const int* __restrict__ rows, const int* __restrict__ cols,
    const float* __restrict__ vals)
{
    int e = blockIdx.x * blockDim.x + threadIdx.x;
    if (e >= EADJ) return;
    int p = atomicAdd(&g_cursor[rows[e]], 1);
    g_csr[p] = make_int2(cols[e], __float_as_int(vals[e]));
}

// ---------------- CSR SpMM (half gather, 1 row/warp) + fused BN stats --------
__global__ __launch_bounds__(256) void spmm_csr(
    const __half2* __restrict__ S2, float* __restrict__ Out,
    float* __restrict__ statpart)
{
    int lane = threadIdx.x & 31;
    int w    = threadIdx.x >> 5;
    int cg   = lane << 2;
    const int h2off = lane << 1;
    int row  = blockIdx.x * 8 + w;

    float4 s = make_float4(0.f, 0.f, 0.f, 0.f);
    float4 q = make_float4(0.f, 0.f, 0.f, 0.f);

    if (row < NN) {
        int e0 = g_rowstart[row];
        int e1 = g_rowstart[row + 1];
        float4 acc = make_float4(0.f, 0.f, 0.f, 0.f);
        int i = e0;
        for (; i + 4 <= e1; i += 4) {
            int2 cv0 = g_csr[i + 0];
            int2 cv1 = g_csr[i + 1];
            int2 cv2 = g_csr[i + 2];
            int2 cv3 = g_csr[i + 3];
            uint2 r0 = *(const uint2*)(S2 + (size_t)cv0.x * (DD / 2) + h2off);
            uint2 r1 = *(const uint2*)(S2 + (size_t)cv1.x * (DD / 2) + h2off);
            uint2 r2 = *(const uint2*)(S2 + (size_t)cv2.x * (DD / 2) + h2off);
            uint2 r3 = *(const uint2*)(S2 + (size_t)cv3.x * (DD / 2) + h2off);
            float v0 = __int_as_float(cv0.y), v1 = __int_as_float(cv1.y);
            float v2 = __int_as_float(cv2.y), v3 = __int_as_float(cv3.y);
            float2 a0 = __half22float2(*(__half2*)&r0.x), b0 = __half22float2(*(__half2*)&r0.y);
            float2 a1 = __half22float2(*(__half2*)&r1.x), b1 = __half22float2(*(__half2*)&r1.y);
            float2 a2 = __half22float2(*(__half2*)&r2.x), b2 = __half22float2(*(__half2*)&r2.y);
            float2 a3 = __half22float2(*(__half2*)&r3.x), b3 = __half22float2(*(__half2*)&r3.y);
            acc.x += v0 * a0.x + v1 * a1.x + v2 * a2.x + v3 * a3.x;
            acc.y += v0 * a0.y + v1 * a1.y + v2 * a2.y + v3 * a3.y;
            acc.z += v0 * b0.x + v1 * b1.x + v2 * b2.x + v3 * b3.x;
            acc.w += v0 * b0.y + v1 * b1.y + v2 * b2.y + v3 * b3.y;
        }
        for (; i < e1; i++) {
            int2 cv = g_csr[i];
            float vv = __int_as_float(cv.y);
            uint2 rr = *(const uint2*)(S2 + (size_t)cv.x * (DD / 2) + h2off);
            float2 aa = __half22float2(*(__half2*)&rr.x);
            float2 bbv = __half22float2(*(__half2*)&rr.y);
            acc.x += vv * aa.x; acc.y += vv * aa.y;
            acc.z += vv * bbv.x; acc.w += vv * bbv.y;
        }
        float4* p = (float4*)(Out + (size_t)row * DD + cg);
        float4 t = *p;
        t.x += acc.x; t.y += acc.y; t.z += acc.z; t.w += acc.w;
        *p = t;
        s = t;
        q.x = t.x * t.x; q.y = t.y * t.y;
        q.z = t.z * t.z; q.w = t.w * t.w;
    }

    __shared__ float4 ss[8][32];
    __shared__ float4 qq[8][32];
    ss[w][lane] = s;
    qq[w][lane] = q;
    __syncthreads();
    if (w == 0) {
#pragma unroll
        for (int k = 1; k < 8; k++) {
            float4 a = ss[k][lane], b = qq[k][lane];
            s.x += a.x; s.y += a.y; s.z += a.z; s.w += a.w;
            q.x += b.x; q.y += b.y; q.z += b.z; q.w += b.w;
        }
        float* base = statpart + (size_t)(blockIdx.x & (NCOPY - 1)) * 2 * DD;
        atomicAdd((float4*)(base + cg), s);
        atomicAdd((float4*)(base + DD + cg), q);
    }
}

// fold NCOPY partials -> BN scale/shift
__global__ __launch_bounds__(128) void reduce_stats(
    const float* __restrict__ statpart,
    const float* __restrict__ gm, const float* __restrict__ be,
    float* __restrict__ ab)
{
    int col = threadIdx.x;
    float s = 0.f, q = 0.f;
#pragma unroll
    for (int c = 0; c < NCOPY; c++) {
        s += statpart[c * 2 * DD + col];
        q += statpart[c * 2 * DD + DD + col];
    }
    const float invN = 1.0f / (float)NN;
    float m   = s * invN;
    float var = q * invN - m * m;
    float a   = gm[col] * rsqrtf(var + BNEPS);
    ab[col]      = a;
    ab[DD + col] = be[col] - m * a;
}

// ---------------- node scores (BN layer2 fused) -------------------------------
__global__ __launch_bounds__(256) void node_scores(
    const float* __restrict__ T2,
    const float* __restrict__ ab,
    const float* __restrict__ X,
    const float* __restrict__ Wc)
{
    int warp = (blockIdx.x * blockDim.x + threadIdx.x) >> 5;
    int lane = threadIdx.x & 31;
    if (warp >= NN) return;
    int cg = lane << 2;
    size_t off = (size_t)warp * DD + cg;
    float4 t = *(const float4*)(T2 + off);
    float4 x = *(const float4*)(X + off);
    float4 a4 = *(const float4*)(ab + cg);
    float4 b4 = *(const float4*)(ab + DD + cg);
    float h0 = fmaxf(0.f, fmaf(t.x, a4.x, b4.x)) + x.x;
    float h1 = fmaxf(0.f, fmaf(t.y, a4.y, b4.y)) + x.y;
    float h2 = fmaxf(0.f, fmaf(t.z, a4.z, b4.z)) + x.z;
    float h3 = fmaxf(0.f, fmaf(t.w, a4.w, b4.w)) + x.w;
    float4 w1 = *(const float4*)(Wc + cg);
    float4 w2 = *(const float4*)(Wc + DD + cg);
    float s1 = h0 * w1.x + h1 * w1.y + h2 * w1.z + h3 * w1.w;
    float s2 = h0 * w2.x + h1 * w2.y + h2 * w2.z + h3 * w2.w;
#pragma unroll
    for (int o = 16; o; o >>= 1) {
        s1 += __shfl_xor_sync(0xFFFFFFFFu, s1, o);
        s2 += __shfl_xor_sync(0xFFFFFFFFu, s2, o);
    }
    if (lane == 0) {
        g_s1[warp] = s1;
        g_s2[warp] = s2;
    }
}

// ---------------- edge prediction ---------------------------------------------
__global__ __launch_bounds__(256) void edge_pred(
    const int* __restrict__ ei,
    const float* __restrict__ bc,
    float* __restrict__ out)
{
    int e = blockIdx.x * blockDim.x + threadIdx.x;
    if (e >= EPRED) return;
    float z = g_s1[ei[e]] + g_s2[ei[e + EPRED]] + bc[0];
    out[e] = 1.0f / (1.0f + expf(-z));
}

// ---------------- launch ------------------------------------------------------
extern "C" void kernel_launch(void* const* d_in, const int* in_sizes, int n_in,
                              void* d_out, int out_size)
{
    const float* x       = (const float*)d_in[0];
    const int*   adj_row = (const int*)d_in[1];
    const int*   adj_col = (const int*)d_in[2];
    const float* adj_val = (const float*)d_in[3];
    const int*   eidx    = (const int*)d_in[4];
    const float* W       = (const float*)d_in[5];
    const float* Wself   = (const float*)d_in[6];
    const float* b       = (const float*)d_in[7];
    const float* gamma   = (const float*)d_in[8];
    const float* beta    = (const float*)d_in[9];
    const float* Wc      = (const float*)d_in[10];
    const float* bc      = (const float*)d_in[11];
    float* out           = (float*)d_out;

    __half2* suppH; float *tmp, *tmp2, *statpart, *bnab;
    int *counts, *flags;
    cudaGetSymbolAddress((void**)&suppH,    g_supp_h);
    cudaGetSymbolAddress((void**)&tmp,      g_tmp);
    cudaGetSymbolAddress((void**)&tmp2,     g_tmp2);
    cudaGetSymbolAddress((void**)&statpart, g_statpart);
    cudaGetSymbolAddress((void**)&bnab,     g_bnab);
    cudaGetSymbolAddress((void**)&counts,   g_counts);
    cudaGetSymbolAddress((void**)&flags,    g_scan_flag);

    const int gemm_smem = 2 * DD * SH * (int)sizeof(__half);   // B + A = 68KB
    cudaFuncSetAttribute(gemm_h,
                         cudaFuncAttributeMaxDynamicSharedMemorySize, gemm_smem);

    const dim3 gemm_grid(GEMX, 2);
    const int eb = (EADJ + 255) / 256;
    const int spmm_blocks = (NN + 7) / 8;

    cudaMemsetAsync(counts, 0, NN * sizeof(int));
    cudaMemsetAsync(flags, 0, SCANB * sizeof(int));
    cudaMemsetAsync(statpart, 0, 2 * NCOPY * 2 * DD * sizeof(float));

    // CSR build
    histo<<<eb, 256>>>(adj_row);
    scan_lookback<<<SCANB, 256>>>();
    scatter_csr<<<eb, 256>>>(adj_row, adj_col, adj_val);

    // layer 1: x -> suppH, tmp
    gemm_h<<<gemm_grid, 256, gemm_smem>>>(x, W, Wself, b, nullptr, suppH, tmp);
    spmm_csr<<<spmm_blocks, 256>>>(suppH, tmp, statpart);
    reduce_stats<<<1, 128>>>(statpart, gamma, beta, bnab);

    // layer 2: tmp -> suppH, tmp2  (distinct buffers: no read/write race)
    gemm_h<<<gemm_grid, 256, gemm_smem>>>(tmp, W + DD * DD, Wself + DD * DD,
                                          b + DD, bnab, suppH, tmp2);
    spmm_csr<<<spmm_blocks, 256>>>(suppH, tmp2, statpart + NCOPY * 2 * DD);
    reduce_stats<<<1, 128>>>(statpart + NCOPY * 2 * DD, gamma + DD, beta + DD,
                             bnab + 2 * DD);

    node_scores<<<(NN * 32 + 255) / 256, 256>>>(tmp2, bnab + 2 * DD, x, Wc);
    edge_pred<<<(EPRED + 255) / 256, 256>>>(eidx, bc, out);
}

// round 14
// speedup vs baseline: 1.3458x; 1.0335x over previous
#include <cuda_runtime.h>
#include <cuda_fp16.h>
#include <math.h>
#include <stdint.h>

#define NN    50000
#define DD    128
#define EADJ  800000
#define EPRED 500000
#define BNEPS 1e-5f
#define SCANB 196          // ceil(NN/256)
#define NCOPY 32           // stat partial copies
#define SH    136          // smem half-stride per row (u32 stride 68)
#define TILES 391          // ceil(NN/128)
#define GEMC  148          // persistent CTAs (1/SM)

// ---------------- scratch ----------------------------------------------------
__device__ __half2 g_supp_h[NN * (DD / 2)];    // fp16 support
__device__ float g_tmp[NN * DD];               // layer-1 pre-BN output
__device__ float g_tmp2[NN * DD];              // layer-2 pre-BN output
__device__ float g_statpart[2 * NCOPY * 2 * DD];
__device__ float g_bnab[2 * 2 * DD];           // [layer][a(128) | b(128)]
__device__ float g_s1[NN];
__device__ float g_s2[NN];
__device__ int   g_counts[NN];
__device__ int   g_rowstart[NN + 1];
__device__ int   g_cursor[NN];
__device__ int   g_scan_flag[SCANB];
__device__ int   g_scan_agg[SCANB];
__device__ int   g_scan_pref[SCANB];
__device__ int2  g_csr[EADJ];                  // (col, fp32 val bits)

// ---------------- helpers ----------------------------------------------------
__device__ __forceinline__ void mma_f16(float* c, const uint32_t* a, const uint32_t* b) {
    asm volatile(
        "mma.sync.aligned.m16n8k16.row.col.f32.f16.f16.f32 "
        "{%0,%1,%2,%3}, {%4,%5,%6,%7}, {%8,%9}, {%0,%1,%2,%3};\n"
        : "+f"(c[0]), "+f"(c[1]), "+f"(c[2]), "+f"(c[3])
        : "r"(a[0]), "r"(a[1]), "r"(a[2]), "r"(a[3]), "r"(b[0]), "r"(b[1]));
}

// ---------------- merged fp16 persistent dual GEMM ---------------------------
// ONE CTA per tile computes BOTH support = A@W (half) and outtmp = A@Wself + b.
// grid 148, 256 threads = 8 warps (wy 2 x wx 4), warp tile 64x32 per matrix.
// Both B matrices resident in smem; A double-buffered with register prefetch
// of the next tile (uint2 halves, 32 regs) -> one sync per tile.
__global__ __launch_bounds__(256) void gemm_hm(
    const float* __restrict__ A,
    const float* __restrict__ W,
    const float* __restrict__ Wself,
    const float* __restrict__ bias,
    const float* __restrict__ bn_ab,    // null -> no BN on A
    __half2* __restrict__ suppH,
    float* __restrict__ outtmp)
{
    extern __shared__ __half smh[];
    __half* BhW = smh;                   // 128 x SH
    __half* BhS = smh + DD * SH;         // 128 x SH
    __half* As0 = smh + 2 * DD * SH;     // 128 x SH
    __half* As1 = smh + 3 * DD * SH;     // 128 x SH

    const int tid  = threadIdx.x;
    const int wid  = tid >> 5;
    const int lane = tid & 31;
    const int wy   = wid >> 2;           // 0..1: 64-row slice
    const int wx   = wid & 3;            // 0..3: 32-col slice
    const int g    = lane >> 2;
    const int tig  = lane & 3;

    // ---- stage both B matrices once: B[n][k] transposed + converted ----
#pragma unroll
    for (int i = 0; i < 4; i++) {
        int k  = lane;                          // 0..31
        int n0 = (wid + i * 8) << 2;            // 0..124
#pragma unroll
        for (int kc = 0; kc < DD; kc += 32) {
            float4 vw = *(const float4*)(W + (size_t)(kc + k) * DD + n0);
            BhW[(n0 + 0) * SH + kc + k] = __float2half_rn(vw.x);
            BhW[(n0 + 1) * SH + kc + k] = __float2half_rn(vw.y);
            BhW[(n0 + 2) * SH + kc + k] = __float2half_rn(vw.z);
            BhW[(n0 + 3) * SH + kc + k] = __float2half_rn(vw.w);
            float4 vs = *(const float4*)(Wself + (size_t)(kc + k) * DD + n0);
            BhS[(n0 + 0) * SH + kc + k] = __float2half_rn(vs.x);
            BhS[(n0 + 1) * SH + kc + k] = __float2half_rn(vs.y);
            BhS[(n0 + 2) * SH + kc + k] = __float2half_rn(vs.z);
            BhS[(n0 + 3) * SH + kc + k] = __float2half_rn(vs.w);
        }
    }

    // bias fragment (for the Wself output)
    float2 bb[4];
#pragma unroll
    for (int nt = 0; nt < 4; nt++) {
        int col = wx * 32 + nt * 8 + (tig << 1);
        bb[nt] = *(const float2*)(bias + col);
    }

    // per-thread A map: idx = tid + p*256; row = idx>>5 (0..127), kv = (idx&31)*4
    uint2 pf[16];
    const int t0 = blockIdx.x;

    // load + convert tile 0 into registers
#pragma unroll
    for (int p = 0; p < 16; p++) {
        int idx = tid + p * 256;
        int row = idx >> 5, c4 = idx & 31;
        int kv  = c4 << 2;
        int gr  = t0 * 128 + row;
        float4 v = make_float4(0.f, 0.f, 0.f, 0.f);
        if (gr < NN) v = *(const float4*)(A + (size_t)gr * DD + kv);
        if (bn_ab) {
            float4 a4 = *(const float4*)(bn_ab + kv);
            float4 b4 = *(const float4*)(bn_ab + DD + kv);
            v.x = fmaxf(0.f, fmaf(v.x, a4.x, b4.x));
            v.y = fmaxf(0.f, fmaf(v.y, a4.y, b4.y));
            v.z = fmaxf(0.f, fmaf(v.z, a4.z, b4.z));
            v.w = fmaxf(0.f, fmaf(v.w, a4.w, b4.w));
        }
        __half2 h01 = __floats2half2_rn(v.x, v.y);
        __half2 h23 = __floats2half2_rn(v.z, v.w);
        pf[p].x = *(uint32_t*)&h01;
        pf[p].y = *(uint32_t*)&h23;
    }
    // store tile 0
#pragma unroll
    for (int p = 0; p < 16; p++) {
        int idx = tid + p * 256;
        int row = idx >> 5, c4 = idx & 31;
        *(uint2*)(&As0[row * SH + (c4 << 2)]) = pf[p];
    }
    __syncthreads();

    __half* cur = As0;
    __half* nxt = As1;

    for (int t = t0; t < TILES; t += GEMC) {
        const int tn = t + GEMC;
        // ---- prefetch + convert next tile into registers (overlaps MMA) ----
        if (tn < TILES) {
#pragma unroll
            for (int p = 0; p < 16; p++) {
                int idx = tid + p * 256;
                int row = idx >> 5, c4 = idx & 31;
                int kv  = c4 << 2;
                int gr  = tn * 128 + row;
                float4 v = make_float4(0.f, 0.f, 0.f, 0.f);
                if (gr < NN) v = *(const float4*)(A + (size_t)gr * DD + kv);
                if (bn_ab) {
                    float4 a4 = *(const float4*)(bn_ab + kv);
                    float4 b4 = *(const float4*)(bn_ab + DD + kv);
                    v.x = fmaxf(0.f, fmaf(v.x, a4.x, b4.x));
                    v.y = fmaxf(0.f, fmaf(v.y, a4.y, b4.y));
                    v.z = fmaxf(0.f, fmaf(v.z, a4.z, b4.z));
                    v.w = fmaxf(0.f, fmaf(v.w, a4.w, b4.w));
                }
                __half2 h01 = __floats2half2_rn(v.x, v.y);
                __half2 h23 = __floats2half2_rn(v.z, v.w);
                pf[p].x = *(uint32_t*)&h01;
                pf[p].y = *(uint32_t*)&h23;
            }
        }

        // ---- compute both matrices for tile t ----
        const uint32_t* Au  = (const uint32_t*)cur;
        const uint32_t* BuW = (const uint32_t*)BhW;
        const uint32_t* BuS = (const uint32_t*)BhS;

        float accW[4][4][4];
        float accS[4][4][4];
#pragma unroll
        for (int mt = 0; mt < 4; mt++)
#pragma unroll
            for (int nt = 0; nt < 4; nt++)
#pragma unroll
                for (int i = 0; i < 4; i++) { accW[mt][nt][i] = 0.f; accS[mt][nt][i] = 0.f; }

#pragma unroll
        for (int ks = 0; ks < 8; ks++) {
            int kb = ks * 8 + tig;
            uint32_t af[4][4];
#pragma unroll
            for (int mt = 0; mt < 4; mt++) {
                int rb = wy * 64 + mt * 16;
                af[mt][0] = Au[(rb + g) * 68 + kb];
                af[mt][1] = Au[(rb + g + 8) * 68 + kb];
                af[mt][2] = Au[(rb + g) * 68 + kb + 4];
                af[mt][3] = Au[(rb + g + 8) * 68 + kb + 4];
            }
            uint32_t bfW[4][2], bfS[4][2];
#pragma unroll
            for (int nt = 0; nt < 4; nt++) {
                int n = wx * 32 + nt * 8 + g;
                bfW[nt][0] = BuW[n * 68 + kb];
                bfW[nt][1] = BuW[n * 68 + kb + 4];
                bfS[nt][0] = BuS[n * 68 + kb];
                bfS[nt][1] = BuS[n * 68 + kb + 4];
            }
#pragma unroll
            for (int mt = 0; mt < 4; mt++)
#pragma unroll
                for (int nt = 0; nt < 4; nt++) {
                    mma_f16(accW[mt][nt], af[mt], bfW[nt]);
                    mma_f16(accS[mt][nt], af[mt], bfS[nt]);
                }
        }

        // ---- store next tile into spare buffer (cur still safe: done reading) ----
        if (tn < TILES) {
#pragma unroll
            for (int p = 0; p < 16; p++) {
                int idx = tid + p * 256;
                int row = idx >> 5, c4 = idx & 31;
                *(uint2*)(&nxt[row * SH + (c4 << 2)]) = pf[p];
            }
        }

        // ---- epilogue: both outputs ----
        const int m0 = t * 128;
#pragma unroll
        for (int nt = 0; nt < 4; nt++) {
            int col = wx * 32 + nt * 8 + (tig << 1);
#pragma unroll
            for (int mt = 0; mt < 4; mt++) {
                int r0 = m0 + wy * 64 + mt * 16 + g;
                int r1 = r0 + 8;
                if (r0 < NN) {
                    float2 w0 = make_float2(accW[mt][nt][0], accW[mt][nt][1]);
                    suppH[(size_t)r0 * (DD / 2) + (col >> 1)] = __float22half2_rn(w0);
                    float2 s0 = make_float2(accS[mt][nt][0] + bb[nt].x, accS[mt][nt][1] + bb[nt].y);
                    *(float2*)(outtmp + (size_t)r0 * DD + col) = s0;
                }
                if (r1 < NN) {
                    float2 w1 = make_float2(accW[mt][nt][2], accW[mt][nt][3]);
                    suppH[(size_t)r1 * (DD / 2) + (col >> 1)] = __float22half2_rn(w1);
                    float2 s1 = make_float2(accS[mt][nt][2] + bb[nt].x, accS[mt][nt][3] + bb[nt].y);
                    *(float2*)(outtmp + (size_t)r1 * DD + col) = s1;
                }
            }
        }
        __syncthreads();
        __half* tp = cur; cur = nxt; nxt = tp;
    }
}

// ---------------- CSR build ---------------------------------------------------
__global__ __launch_bounds__(256) void histo(const int* __restrict__ rows)
{
    int e = blockIdx.x * blockDim.x + threadIdx.x;
    if (e < EADJ) atomicAdd(&g_counts[rows[e]], 1);
}

__global__ __launch_bounds__(256) void scan_lookback()
{
    __shared__ int ws[8];
    __shared__ int s_prefix;
    const int bid = blockIdx.x;
    const int tid = threadIdx.x, lane = tid & 31, w = tid >> 5;
    int i = bid * 256 + tid;
    int v = (i < NN) ? g_counts[i] : 0;
    int inc = v;
#pragma unroll
    for (int o = 1; o < 32; o <<= 1) {
        int n = __shfl_up_sync(0xFFFFFFFFu, inc, o);
        if (lane >= o) inc += n;
    }
    if (lane == 31) ws[w] = inc;
    __syncthreads();
    if (w == 0 && lane < 8) {
        int s = ws[lane];
#pragma unroll
        for (int o = 1; o < 8; o <<= 1) {
            int n = __shfl_up_sync(0xFFu, s, o);
            if (lane >= o) s += n;
        }
        ws[lane] = s;
    }
    __syncthreads();
    int local_excl = (w ? ws[w - 1] : 0) + inc - v;
    int total = ws[7];

    if (tid == 0) {
        if (bid == 0) {
            g_scan_pref[0] = total;
            __threadfence();
            g_scan_flag[0] = 2;
            s_prefix = 0;
        } else {
            g_scan_agg[bid] = total;
            __threadfence();
            g_scan_flag[bid] = 1;
            int pref = 0;
            for (int j = bid - 1; j >= 0; j--) {
                int f;
                do { f = *(volatile int*)&g_scan_flag[j]; } while (f == 0);
                __threadfence();
                if (f == 2) { pref += *(volatile int*)&g_scan_pref[j]; break; }
                pref += *(volatile int*)&g_scan_agg[j];
            }
            g_scan_pref[bid] = pref + total;
            __threadfence();
            g_scan_flag[bid] = 2;
            s_prefix = pref;
        }
    }
    __syncthreads();
    int excl = s_prefix + local_excl;
    if (i < NN) { g_rowstart[i] = excl; g_cursor[i] = excl; }
    if (i == 0) g_rowstart[NN] = EADJ;
}

__global__ __launch_bounds__(256) void scatter_csr(
    const int* __restrict__ rows, const int* __restrict__ cols,
    const float* __restrict__ vals)
{
    int e = blockIdx.x * blockDim.x + threadIdx.x;
    if (e >= EADJ) return;
    int p = atomicAdd(&g_cursor[rows[e]], 1);
    g_csr[p] = make_int2(cols[e], __float_as_int(vals[e]));
}

// ---------------- CSR SpMM (half gather, 1 row/warp) + fused BN stats --------
__global__ __launch_bounds__(256) void spmm_csr(
    const __half2* __restrict__ S2, float* __restrict__ Out,
    float* __restrict__ statpart)
{
    int lane = threadIdx.x & 31;
    int w    = threadIdx.x >> 5;
    int cg   = lane << 2;
    const int h2off = lane << 1;
    int row  = blockIdx.x * 8 + w;

    float4 s = make_float4(0.f, 0.f, 0.f, 0.f);
    float4 q = make_float4(0.f, 0.f, 0.f, 0.f);

    if (row < NN) {
        int e0 = g_rowstart[row];
        int e1 = g_rowstart[row + 1];
        float4 acc = make_float4(0.f, 0.f, 0.f, 0.f);
        int i = e0;
        for (; i + 4 <= e1; i += 4) {
            int2 cv0 = g_csr[i + 0];
            int2 cv1 = g_csr[i + 1];
            int2 cv2 = g_csr[i + 2];
            int2 cv3 = g_csr[i + 3];
            uint2 r0 = *(const uint2*)(S2 + (size_t)cv0.x * (DD / 2) + h2off);
            uint2 r1 = *(const uint2*)(S2 + (size_t)cv1.x * (DD / 2) + h2off);
            uint2 r2 = *(const uint2*)(S2 + (size_t)cv2.x * (DD / 2) + h2off);
            uint2 r3 = *(const uint2*)(S2 + (size_t)cv3.x * (DD / 2) + h2off);
            float v0 = __int_as_float(cv0.y), v1 = __int_as_float(cv1.y);
            float v2 = __int_as_float(cv2.y), v3 = __int_as_float(cv3.y);
            float2 a0 = __half22float2(*(__half2*)&r0.x), b0 = __half22float2(*(__half2*)&r0.y);
            float2 a1 = __half22float2(*(__half2*)&r1.x), b1 = __half22float2(*(__half2*)&r1.y);
            float2 a2 = __half22float2(*(__half2*)&r2.x), b2 = __half22float2(*(__half2*)&r2.y);
            float2 a3 = __half22float2(*(__half2*)&r3.x), b3 = __half22float2(*(__half2*)&r3.y);
            acc.x += v0 * a0.x + v1 * a1.x + v2 * a2.x + v3 * a3.x;
            acc.y += v0 * a0.y + v1 * a1.y + v2 * a2.y + v3 * a3.y;
            acc.z += v0 * b0.x + v1 * b1.x + v2 * b2.x + v3 * b3.x;
            acc.w += v0 * b0.y + v1 * b1.y + v2 * b2.y + v3 * b3.y;
        }
        for (; i < e1; i++) {
            int2 cv = g_csr[i];
            float vv = __int_as_float(cv.y);
            uint2 rr = *(const uint2*)(S2 + (size_t)cv.x * (DD / 2) + h2off);
            float2 aa = __half22float2(*(__half2*)&rr.x);
            float2 bbv = __half22float2(*(__half2*)&rr.y);
            acc.x += vv * aa.x; acc.y += vv * aa.y;
            acc.z += vv * bbv.x; acc.w += vv * bbv.y;
        }
        float4* p = (float4*)(Out + (size_t)row * DD + cg);
        float4 t = *p;
        t.x += acc.x; t.y += acc.y; t.z += acc.z; t.w += acc.w;
        *p = t;
        s = t;
        q.x = t.x * t.x; q.y = t.y * t.y;
        q.z = t.z * t.z; q.w = t.w * t.w;
    }

    __shared__ float4 ss[8][32];
    __shared__ float4 qq[8][32];
    ss[w][lane] = s;
    qq[w][lane] = q;
    __syncthreads();
    if (w == 0) {
#pragma unroll
        for (int k = 1; k < 8; k++) {
            float4 a = ss[k][lane], b = qq[k][lane];
            s.x += a.x; s.y += a.y; s.z += a.z; s.w += a.w;
            q.x += b.x; q.y += b.y; q.z += b.z; q.w += b.w;
        }
        float* base = statpart + (size_t)(blockIdx.x & (NCOPY - 1)) * 2 * DD;
        atomicAdd((float4*)(base + cg), s);
        atomicAdd((float4*)(base + DD + cg), q);
    }
}

// fold NCOPY partials -> BN scale/shift
__global__ __launch_bounds__(128) void reduce_stats(
    const float* __restrict__ statpart,
    const float* __restrict__ gm, const float* __restrict__ be,
    float* __restrict__ ab)
{
    int col = threadIdx.x;
    float s = 0.f, q = 0.f;
#pragma unroll
    for (int c = 0; c < NCOPY; c++) {
        s += statpart[c * 2 * DD + col];
        q += statpart[c * 2 * DD + DD + col];
    }
    const float invN = 1.0f / (float)NN;
    float m   = s * invN;
    float var = q * invN - m * m;
    float a   = gm[col] * rsqrtf(var + BNEPS);
    ab[col]      = a;
    ab[DD + col] = be[col] - m * a;
}

// ---------------- node scores (BN layer2 fused) -------------------------------
__global__ __launch_bounds__(256) void node_scores(
    const float* __restrict__ T2,
    const float* __restrict__ ab,
    const float* __restrict__ X,
    const float* __restrict__ Wc)
{
    int warp = (blockIdx.x * blockDim.x + threadIdx.x) >> 5;
    int lane = threadIdx.x & 31;
    if (warp >= NN) return;
    int cg = lane << 2;
    size_t off = (size_t)warp * DD + cg;
    float4 t = *(const float4*)(T2 + off);
    float4 x = *(const float4*)(X + off);
    float4 a4 = *(const float4*)(ab + cg);
    float4 b4 = *(const float4*)(ab + DD + cg);
    float h0 = fmaxf(0.f, fmaf(t.x, a4.x, b4.x)) + x.x;
    float h1 = fmaxf(0.f, fmaf(t.y, a4.y, b4.y)) + x.y;
    float h2 = fmaxf(0.f, fmaf(t.z, a4.z, b4.z)) + x.z;
    float h3 = fmaxf(0.f, fmaf(t.w, a4.w, b4.w)) + x.w;
    float4 w1 = *(const float4*)(Wc + cg);
    float4 w2 = *(const float4*)(Wc + DD + cg);
    float s1 = h0 * w1.x + h1 * w1.y + h2 * w1.z + h3 * w1.w;
    float s2 = h0 * w2.x + h1 * w2.y + h2 * w2.z + h3 * w2.w;
#pragma unroll
    for (int o = 16; o; o >>= 1) {
        s1 += __shfl_xor_sync(0xFFFFFFFFu, s1, o);
        s2 += __shfl_xor_sync(0xFFFFFFFFu, s2, o);
    }
    if (lane == 0) {
        g_s1[warp] = s1;
        g_s2[warp] = s2;
    }
}

// ---------------- edge prediction ---------------------------------------------
__global__ __launch_bounds__(256) void edge_pred(
    const int* __restrict__ ei,
    const float* __restrict__ bc,
    float* __restrict__ out)
{
    int e = blockIdx.x * blockDim.x + threadIdx.x;
    if (e >= EPRED) return;
    float z = g_s1[ei[e]] + g_s2[ei[e + EPRED]] + bc[0];
    out[e] = 1.0f / (1.0f + expf(-z));
}

// ---------------- launch ------------------------------------------------------
extern "C" void kernel_launch(void* const* d_in, const int* in_sizes, int n_in,
                              void* d_out, int out_size)
{
    const float* x       = (const float*)d_in[0];
    const int*   adj_row = (const int*)d_in[1];
    const int*   adj_col = (const int*)d_in[2];
    const float* adj_val = (const float*)d_in[3];
    const int*   eidx    = (const int*)d_in[4];
    const float* W       = (const float*)d_in[5];
    const float* Wself   = (const float*)d_in[6];
    const float* b       = (const float*)d_in[7];
    const float* gamma   = (const float*)d_in[8];
    const float* beta    = (const float*)d_in[9];
    const float* Wc      = (const float*)d_in[10];
    const float* bc      = (const float*)d_in[11];
    float* out           = (float*)d_out;

    __half2* suppH; float *tmp, *tmp2, *statpart, *bnab;
    int *counts, *flags;
    cudaGetSymbolAddress((void**)&suppH,    g_supp_h);
    cudaGetSymbolAddress((void**)&tmp,      g_tmp);
    cudaGetSymbolAddress((void**)&tmp2,     g_tmp2);
    cudaGetSymbolAddress((void**)&statpart, g_statpart);
    cudaGetSymbolAddress((void**)&bnab,     g_bnab);
    cudaGetSymbolAddress((void**)&counts,   g_counts);
    cudaGetSymbolAddress((void**)&flags,    g_scan_flag);

    const int gemm_smem = 4 * DD * SH * (int)sizeof(__half);   // 2 B + 2 A bufs
    cudaFuncSetAttribute(gemm_hm,
                         cudaFuncAttributeMaxDynamicSharedMemorySize, gemm_smem);

    const int eb = (EADJ + 255) / 256;
    const int spmm_blocks = (NN + 7) / 8;

    cudaMemsetAsync(counts, 0, NN * sizeof(int));
    cudaMemsetAsync(flags, 0, SCANB * sizeof(int));
    cudaMemsetAsync(statpart, 0, 2 * NCOPY * 2 * DD * sizeof(float));

    // CSR build
    histo<<<eb, 256>>>(adj_row);
    scan_lookback<<<SCANB, 256>>>();
    scatter_csr<<<eb, 256>>>(adj_row, adj_col, adj_val);

    // layer 1: x -> suppH, tmp
    gemm_hm<<<GEMC, 256, gemm_smem>>>(x, W, Wself, b, nullptr, suppH, tmp);
    spmm_csr<<<spmm_blocks, 256>>>(suppH, tmp, statpart);
    reduce_stats<<<1, 128>>>(statpart, gamma, beta, bnab);

    // layer 2: tmp -> suppH, tmp2  (distinct buffers: no aliasing)
    gemm_hm<<<GEMC, 256, gemm_smem>>>(tmp, W + DD * DD, Wself + DD * DD,
                                      b + DD, bnab, suppH, tmp2);
    spmm_csr<<<spmm_blocks, 256>>>(suppH, tmp2, statpart + NCOPY * 2 * DD);
    reduce_stats<<<1, 128>>>(statpart + NCOPY * 2 * DD, gamma + DD, beta + DD,
                             bnab + 2 * DD);

    node_scores<<<(NN * 32 + 255) / 256, 256>>>(tmp2, bnab + 2 * DD, x, Wc);
    edge_pred<<<(EPRED + 255) / 256, 256>>>(eidx, bc, out);
}